// round 6
// baseline (speedup 1.0000x reference)
#include <cuda_runtime.h>
#include <cuda_bf16.h>
#include <math.h>
#include <stdint.h>

// Problem constants
#define BB 2
#define TT 2048
#define CC 1024
#define HH 16
#define DD 64
#define MTOT 4096
#define K2 2048                // [hi | lo] packed K dimension
#define WSZ2 (CC * K2)

// ---------------------------------------------------------------------------
// Device scratch — all operand tensors stored as unique [hi | lo] halves.
// ---------------------------------------------------------------------------
__device__ __align__(128) __nv_bfloat16 g_xs[(size_t)MTOT * K2];        // x:   [xh | xl]
__device__ __align__(128) __nv_bfloat16 g_wcat[(size_t)4 * WSZ2];       // w*:  [Wh | Wl]
__device__ __align__(128) __nv_bfloat16 g_atts[(size_t)MTOT * K2];      // att: [ah | al]
__device__ __align__(128) __nv_bfloat16 g_qs[(size_t)BB * HH * TT * 128]; // Q' = [Qh|Ql]*0.125
__device__ __align__(128) __nv_bfloat16 g_ks[(size_t)BB * HH * TT * 128]; // K' = [Kh|Kl]
__device__ __align__(128) __nv_bfloat16 g_vs[(size_t)BB * HH * TT * 128]; // V' = [Vh|Vl]

// ---------------------------------------------------------------------------
// PTX helpers (sm_80-class ISA: compiles under compute_103)
// ---------------------------------------------------------------------------
__device__ __forceinline__ uint32_t smem_u32(const void* p) {
    return (uint32_t)__cvta_generic_to_shared(p);
}

__device__ __forceinline__ void cp16(uint32_t dst, const void* src) {
    asm volatile("cp.async.cg.shared.global [%0], [%1], 16;" :: "r"(dst), "l"(src));
}
#define CP_COMMIT() asm volatile("cp.async.commit_group;" ::: "memory")
#define CP_WAIT0()  asm volatile("cp.async.wait_group 0;" ::: "memory")
#define CP_WAIT1()  asm volatile("cp.async.wait_group 1;" ::: "memory")

__device__ __forceinline__ void ldm_x4(uint32_t* r, uint32_t addr) {
    asm volatile("ldmatrix.sync.aligned.m8n8.x4.shared.b16 {%0,%1,%2,%3}, [%4];"
                 : "=r"(r[0]), "=r"(r[1]), "=r"(r[2]), "=r"(r[3]) : "r"(addr));
}
__device__ __forceinline__ void ldm_x4_t(uint32_t* r, uint32_t addr) {
    asm volatile("ldmatrix.sync.aligned.m8n8.x4.trans.shared.b16 {%0,%1,%2,%3}, [%4];"
                 : "=r"(r[0]), "=r"(r[1]), "=r"(r[2]), "=r"(r[3]) : "r"(addr));
}

__device__ __forceinline__ void mma16816(float* c, const uint32_t* a, const uint32_t* b) {
    asm volatile(
        "mma.sync.aligned.m16n8k16.row.col.f32.bf16.bf16.f32 "
        "{%0,%1,%2,%3}, {%4,%5,%6,%7}, {%8,%9}, {%0,%1,%2,%3};"
        : "+f"(c[0]), "+f"(c[1]), "+f"(c[2]), "+f"(c[3])
        : "r"(a[0]), "r"(a[1]), "r"(a[2]), "r"(a[3]), "r"(b[0]), "r"(b[1]));
}

__device__ __forceinline__ uint32_t pack2(__nv_bfloat16 a, __nv_bfloat16 b) {
    union { __nv_bfloat162 v; uint32_t u; } t;
    t.v = __halves2bfloat162(a, b);
    return t.u;
}
__device__ __forceinline__ void split2(float v, __nv_bfloat16& h, __nv_bfloat16& l) {
    h = __float2bfloat16(v);
    l = __float2bfloat16(v - __bfloat162float(h));
}

// ---------------------------------------------------------------------------
// bf16 hi/lo split: out row = [hi(1024) | lo(1024)].
// Products used downstream: h·h' + l·h' + h·l'  == fp32 to ~2^-17.
// ---------------------------------------------------------------------------
__device__ __forceinline__ void split_row(const float* __restrict__ in,
                                          __nv_bfloat16* __restrict__ out,
                                          size_t r, int k)
{
    float4 v = *reinterpret_cast<const float4*>(in + r * CC + k);
    float f[4] = {v.x, v.y, v.z, v.w};
    __nv_bfloat16 hi[4], lo[4];
#pragma unroll
    for (int i = 0; i < 4; i++) split2(f[i], hi[i], lo[i]);
    uint2 hp = make_uint2(pack2(hi[0], hi[1]), pack2(hi[2], hi[3]));
    uint2 lp = make_uint2(pack2(lo[0], lo[1]), pack2(lo[2], lo[3]));
    __nv_bfloat16* o = out + r * K2 + k;
    *reinterpret_cast<uint2*>(o)      = hp;
    *reinterpret_cast<uint2*>(o + CC) = lp;
}

__global__ __launch_bounds__(256) void split_x_kernel(const float* __restrict__ in,
                                                      __nv_bfloat16* __restrict__ out)
{
    split_row(in, out, blockIdx.x, threadIdx.x * 4);
}

struct W4 { const float* in[4]; };
__global__ __launch_bounds__(256) void split_w4_kernel(W4 p)
{
    const int w = blockIdx.y;
    split_row(p.in[w], g_wcat + (size_t)w * WSZ2, blockIdx.x, threadIdx.x * 4);
}

// ---------------------------------------------------------------------------
// HMMA GEMM: out[m,n] = sum_k A[m,k]*W[n,k] + bias[n]
// A,W stored [rows x 2048] = [hi|lo]. CTA 128x128, 8 warps (2x4), warp tile
// 64x32. K chunk = 32 unique k; smem stage row = [h(64B) | l(64B)] = 128B.
// 3 products per k16 from 4 fragment sets: ah*bh + al*bh + ah*bl.
// KIND 0: fp32 out [M,C].  KIND 1 (QKV): z selects Q'/K'/V' [h|l] target.
// ---------------------------------------------------------------------------
struct GemmP {
    const __nv_bfloat16* A;
    const __nv_bfloat16* W[3];
    const float* bias[3];
    float* fout;
};

#define GEMM_NCH 32
#define GEMM_STAGE 32768       // A tile 16KB + W tile 16KB
#define GEMM_SMEM (3 * GEMM_STAGE)

template <int KIND>
__global__ __launch_bounds__(256, 2) void hmma_gemm(GemmP p)
{
    const int z = blockIdx.z;
    const __nv_bfloat16* __restrict__ A = p.A;
    const __nv_bfloat16* __restrict__ W = p.W[z];
    const float* __restrict__ bias = p.bias[z];

    extern __shared__ __align__(1024) char smem[];
    const uint32_t sbase = smem_u32(smem);

    const int m0 = blockIdx.y * 128, n0 = blockIdx.x * 128;
    const int tid = threadIdx.x, lane = tid & 31, wid = tid >> 5;
    const int wm = wid >> 2, wn = wid & 3;

    const __nv_bfloat16* Arow = A + (size_t)m0 * K2;
    const __nv_bfloat16* Wrow = W + (size_t)n0 * K2;

    auto prefetch = [&](int c, int buf) {
        if (c < GEMM_NCH) {
            const uint32_t dst0 = sbase + buf * GEMM_STAGE;
#pragma unroll
            for (int it = 0; it < 8; ++it) {
                const int idx = tid + it * 256;        // 0..2047
                const int mat = idx >> 10;             // 0 = A, 1 = W
                const int rem = idx & 1023;
                const int r = rem >> 3, ch = rem & 7;
                // smem row r = [h(4x16B) | l(4x16B)]; hi at ch<4, lo at ch>=4
                const int col = c * 32 + (ch & 3) * 8 + (ch >> 2) * CC;
                const __nv_bfloat16* src =
                    (mat ? Wrow : Arow) + (size_t)r * K2 + col;
                cp16(dst0 + mat * 16384 + r * 128 + ((uint32_t)(ch ^ (r & 7)) << 4), src);
            }
        }
        CP_COMMIT();
    };

    float acc[4][4][4];
#pragma unroll
    for (int i = 0; i < 4; i++)
#pragma unroll
        for (int j = 0; j < 4; j++)
#pragma unroll
            for (int q = 0; q < 4; q++) acc[i][j][q] = 0.f;

    prefetch(0, 0);
    prefetch(1, 1);

    for (int kc = 0; kc < GEMM_NCH; ++kc) {
        if (kc == GEMM_NCH - 1) { CP_WAIT0(); } else { CP_WAIT1(); }
        __syncthreads();
        prefetch(kc + 2, (kc + 2) % 3);

        const uint32_t bufA = sbase + (kc % 3) * GEMM_STAGE;
        const uint32_t bufW = bufA + 16384;
#pragma unroll
        for (int kk = 0; kk < 2; ++kk) {
            // A fragments (hi and lo)
            uint32_t ah[4][4], al[4][4];
#pragma unroll
            for (int mt = 0; mt < 4; ++mt) {
                const int r = wm * 64 + mt * 16 + (lane & 15);
                const int ch = kk * 2 + (lane >> 4);
                ldm_x4(ah[mt], bufA + r * 128 + ((uint32_t)(ch ^ (r & 7)) << 4));
                ldm_x4(al[mt], bufA + r * 128 + ((uint32_t)((ch + 4) ^ (r & 7)) << 4));
            }
            // W fragments (hi), then hi*hi + lo*hi
            uint32_t bh[4][2];
#pragma unroll
            for (int pr = 0; pr < 2; ++pr) {
                const int r = wn * 32 + pr * 16 + (lane & 7) + ((lane >> 4) << 3);
                const int ch = kk * 2 + ((lane >> 3) & 1);
                uint32_t t4[4];
                ldm_x4(t4, bufW + r * 128 + ((uint32_t)(ch ^ (r & 7)) << 4));
                bh[pr * 2][0] = t4[0]; bh[pr * 2][1] = t4[1];
                bh[pr * 2 + 1][0] = t4[2]; bh[pr * 2 + 1][1] = t4[3];
            }
#pragma unroll
            for (int mt = 0; mt < 4; ++mt)
#pragma unroll
                for (int nt = 0; nt < 4; ++nt) {
                    mma16816(acc[mt][nt], ah[mt], bh[nt]);
                    mma16816(acc[mt][nt], al[mt], bh[nt]);
                }
            // W lo fragments, hi*lo
            uint32_t bl[4][2];
#pragma unroll
            for (int pr = 0; pr < 2; ++pr) {
                const int r = wn * 32 + pr * 16 + (lane & 7) + ((lane >> 4) << 3);
                const int ch = kk * 2 + ((lane >> 3) & 1) + 4;
                uint32_t t4[4];
                ldm_x4(t4, bufW + r * 128 + ((uint32_t)(ch ^ (r & 7)) << 4));
                bl[pr * 2][0] = t4[0]; bl[pr * 2][1] = t4[1];
                bl[pr * 2 + 1][0] = t4[2]; bl[pr * 2 + 1][1] = t4[3];
            }
#pragma unroll
            for (int mt = 0; mt < 4; ++mt)
#pragma unroll
                for (int nt = 0; nt < 4; ++nt)
                    mma16816(acc[mt][nt], ah[mt], bl[nt]);
        }
    }

    // Epilogue
    const int r0g = m0 + wm * 64 + (lane >> 2);
    const int nbase = n0 + wn * 32 + 2 * (lane & 3);
#pragma unroll
    for (int mt = 0; mt < 4; ++mt) {
        const int m = r0g + mt * 16;
#pragma unroll
        for (int nt = 0; nt < 4; ++nt) {
            const int n = nbase + nt * 8;
            float v0 = acc[mt][nt][0] + bias[n];
            float v1 = acc[mt][nt][1] + bias[n + 1];
            float v2 = acc[mt][nt][2] + bias[n];
            float v3 = acc[mt][nt][3] + bias[n + 1];
            if (KIND == 0) {
                *reinterpret_cast<float2*>(p.fout + (size_t)m * CC + n) = make_float2(v0, v1);
                *reinterpret_cast<float2*>(p.fout + (size_t)(m + 8) * CC + n) = make_float2(v2, v3);
            } else {
                if (z == 0) { v0 *= 0.125f; v1 *= 0.125f; v2 *= 0.125f; v3 *= 0.125f; }
                __nv_bfloat16* target = (z == 0) ? g_qs : (z == 1) ? g_ks : g_vs;
                const int hh = n >> 6, d = n & 63;
#pragma unroll
                for (int rr = 0; rr < 2; ++rr) {
                    const int mm = m + rr * 8;
                    const float a0 = rr ? v2 : v0, a1 = rr ? v3 : v1;
                    const int b = mm >> 11, t = mm & (TT - 1);
                    const size_t row = ((size_t)(b * HH + hh)) * TT + t;
                    __nv_bfloat16 h0, l0, h1, l1;
                    split2(a0, h0, l0);
                    split2(a1, h1, l1);
                    __nv_bfloat16* q = target + row * 128 + d;
                    *(uint32_t*)q        = pack2(h0, h1);
                    *(uint32_t*)(q + 64) = pack2(l0, l1);
                }
            }
        }
    }
}

// ---------------------------------------------------------------------------
// Flash attention on HMMA. CTA: 128 q rows, 8 warps x 16 rows. KV block 64.
// Q tile staged in smem (Qh|Ql, 32KB) — Q fragments ldmatrix'd inside the S
// loop so they never persist in registers. 2-stage KV ring (64KB).
// 2 CTAs/SM (regs capped at 128): doubles warp parallelism to hide the
// MMA -> softmax -> repack dependent chain.
// S = Qh*Kh + Ql*Kh + Qh*Kl (scale pre-folded). P split-2 -> PV with Vh/Vl.
// Output written directly in [ah|al] proj-A layout.
// ---------------------------------------------------------------------------
#define ATT_STAGE 32768                  // Kh|Kl|Vh|Vl tiles of 8KB
#define ATT_Q_OFF (2 * ATT_STAGE)        // 64KB
#define ATT_SMEM  (ATT_Q_OFF + 32768)    // 96KB

__global__ __launch_bounds__(256, 2) void attn_kernel()
{
    extern __shared__ __align__(1024) char smem[];
    const uint32_t sbase = smem_u32(smem);

    const int bh = blockIdx.y;
    const int qb = (int)gridDim.x - 1 - (int)blockIdx.x;  // reversed for balance
    const int q0 = qb * 128;
    const int tid = threadIdx.x, lane = tid & 31, wid = tid >> 5;
    const int qw = q0 + wid * 16;

    const uint32_t Qh = sbase + ATT_Q_OFF;
    const uint32_t Ql = Qh + 16384;

    // Stage Q tile (128 rows x [h 128B | l 128B]) into smem via cp.async.
    {
        const char* qsrc = reinterpret_cast<const char*>(g_qs) +
                           ((size_t)bh * TT + q0) * 256;
#pragma unroll
        for (int it = 0; it < 8; ++it) {
            const int idx = tid + it * 256;       // 0..2047
            const int sub = idx >> 10;            // 0 = h, 1 = l
            const int rem = idx & 1023;
            const int r = rem >> 3, ch = rem & 7;
            cp16(Qh + sub * 16384 + r * 128 + ((uint32_t)(ch ^ (r & 7)) << 4),
                 qsrc + (size_t)r * 256 + sub * 128 + ch * 16);
        }
        CP_COMMIT();
    }

    float o[8][4];
#pragma unroll
    for (int i = 0; i < 8; i++)
#pragma unroll
        for (int j = 0; j < 4; j++) o[i][j] = 0.f;
    float m0r = -INFINITY, m1r = -INFINITY, l0 = 0.f, l1 = 0.f;

    const char* ksrc_base = reinterpret_cast<const char*>(g_ks) + (size_t)bh * TT * 256;
    const char* vsrc_base = reinterpret_cast<const char*>(g_vs) + (size_t)bh * TT * 256;

    const int nblk = 2 * qb + 2;

    auto prefetchKV = [&](int kb, int buf) {
        if (kb < nblk) {
            const uint32_t dst = sbase + buf * ATT_STAGE;
            const char* ks = ksrc_base + (size_t)kb * 64 * 256;
            const char* vs = vsrc_base + (size_t)kb * 64 * 256;
#pragma unroll
            for (int it = 0; it < 8; ++it) {
                const int idx = tid + it * 256;        // 0..2047
                const int mat = idx >> 10;             // 0 = K, 1 = V
                const int rem = idx & 1023;
                const int sub = rem >> 9;              // 0 = hi, 1 = lo
                const int r = (rem >> 3) & 63;
                const int ch = rem & 7;
                const char* src = (mat ? vs : ks) + (size_t)r * 256 + sub * 128 + ch * 16;
                cp16(dst + mat * 16384 + sub * 8192 + r * 128 +
                         ((uint32_t)(ch ^ (r & 7)) << 4), src);
            }
        }
        CP_COMMIT();
    };

    prefetchKV(0, 0);

    for (int kb = 0; kb < nblk; ++kb) {
        CP_WAIT0();
        __syncthreads();
        prefetchKV(kb + 1, (kb + 1) & 1);
        const int kv0 = kb * 64;

        if (kv0 <= qw + 15) {
            const uint32_t Kh = sbase + (kb & 1) * ATT_STAGE;
            const uint32_t Kl = Kh + 8192;
            const uint32_t Vh = Kh + 16384;
            const uint32_t Vl = Kh + 24576;

            // ---- S = Qh*Kh + Ql*Kh + Qh*Kl ----
            float s[8][4];
#pragma unroll
            for (int i = 0; i < 8; i++)
#pragma unroll
                for (int j = 0; j < 4; j++) s[i][j] = 0.f;
#pragma unroll
            for (int d16 = 0; d16 < 4; ++d16) {
                // Q fragments for this d16 chunk (short register live range)
                uint32_t aqh[4], aql[4];
                {
                    const int rq = wid * 16 + (lane & 15);
                    const int chq = d16 * 2 + (lane >> 4);
                    const uint32_t swq = (uint32_t)(chq ^ (rq & 7)) << 4;
                    ldm_x4(aqh, Qh + rq * 128 + swq);
                    ldm_x4(aql, Ql + rq * 128 + swq);
                }
#pragma unroll
                for (int pr = 0; pr < 4; ++pr) {
                    const int r = pr * 16 + (lane & 7) + ((lane >> 4) << 3);
                    const int ch = d16 * 2 + ((lane >> 3) & 1);
                    const uint32_t sw = (uint32_t)(ch ^ (r & 7)) << 4;
                    uint32_t kh4[4];
                    ldm_x4(kh4, Kh + r * 128 + sw);
                    mma16816(s[pr * 2],     aqh, kh4);
                    mma16816(s[pr * 2 + 1], aqh, kh4 + 2);
                    mma16816(s[pr * 2],     aql, kh4);
                    mma16816(s[pr * 2 + 1], aql, kh4 + 2);
                    uint32_t kl4[4];
                    ldm_x4(kl4, Kl + r * 128 + sw);
                    mma16816(s[pr * 2],     aqh, kl4);
                    mma16816(s[pr * 2 + 1], aqh, kl4 + 2);
                }
            }

            const int r0 = qw + (lane >> 2), r1 = r0 + 8;
            if (kv0 + 63 > qw) {  // causal mask region
#pragma unroll
                for (int nt = 0; nt < 8; ++nt) {
                    const int j = kv0 + nt * 8 + 2 * (lane & 3);
                    if (j > r0)     s[nt][0] = -INFINITY;
                    if (j + 1 > r0) s[nt][1] = -INFINITY;
                    if (j > r1)     s[nt][2] = -INFINITY;
                    if (j + 1 > r1) s[nt][3] = -INFINITY;
                }
            }

            // ---- online softmax ----
            float b0 = -INFINITY, b1 = -INFINITY;
#pragma unroll
            for (int nt = 0; nt < 8; ++nt) {
                b0 = fmaxf(b0, fmaxf(s[nt][0], s[nt][1]));
                b1 = fmaxf(b1, fmaxf(s[nt][2], s[nt][3]));
            }
            b0 = fmaxf(b0, __shfl_xor_sync(0xffffffffu, b0, 1));
            b0 = fmaxf(b0, __shfl_xor_sync(0xffffffffu, b0, 2));
            b1 = fmaxf(b1, __shfl_xor_sync(0xffffffffu, b1, 1));
            b1 = fmaxf(b1, __shfl_xor_sync(0xffffffffu, b1, 2));
            const float mn0 = fmaxf(m0r, b0), mn1 = fmaxf(m1r, b1);
            const float cor0 = __expf(m0r - mn0), cor1 = __expf(m1r - mn1);
            m0r = mn0; m1r = mn1;
            l0 *= cor0; l1 *= cor1;
#pragma unroll
            for (int nt = 0; nt < 8; ++nt) {
                o[nt][0] *= cor0; o[nt][1] *= cor0;
                o[nt][2] *= cor1; o[nt][3] *= cor1;
            }

            // ---- P = exp(S - m), split-2, repack C-frag -> A-frag ----
            uint32_t ph[4][4], pl[4][4];
#pragma unroll
            for (int kc = 0; kc < 4; ++kc) {
#pragma unroll
                for (int half = 0; half < 2; ++half) {
                    const int nt = kc * 2 + half;
                    const float p0 = __expf(s[nt][0] - mn0);
                    const float p1 = __expf(s[nt][1] - mn0);
                    const float p2 = __expf(s[nt][2] - mn1);
                    const float p3 = __expf(s[nt][3] - mn1);
                    l0 += p0 + p1; l1 += p2 + p3;
                    __nv_bfloat16 h0, lo0, h1, lo1, h2, lo2, h3, lo3;
                    split2(p0, h0, lo0); split2(p1, h1, lo1);
                    split2(p2, h2, lo2); split2(p3, h3, lo3);
                    ph[kc][half * 2]     = pack2(h0, h1);
                    ph[kc][half * 2 + 1] = pack2(h2, h3);
                    pl[kc][half * 2]     = pack2(lo0, lo1);
                    pl[kc][half * 2 + 1] = pack2(lo2, lo3);
                }
            }

            // ---- O += Ph*Vh + Pl*Vh + Ph*Vl ----
#pragma unroll
            for (int kc = 0; kc < 4; ++kc) {
                const int r = kc * 16 + (lane & 7) + ((lane >> 3) & 1) * 8;
#pragma unroll
                for (int dp = 0; dp < 4; ++dp) {
                    const int ch = dp * 2 + (lane >> 4);
                    const uint32_t sw = (uint32_t)(ch ^ (r & 7)) << 4;
                    uint32_t vh[4], vl[4];
                    ldm_x4_t(vh, Vh + r * 128 + sw);
                    ldm_x4_t(vl, Vl + r * 128 + sw);
                    mma16816(o[dp * 2],     ph[kc], vh);
                    mma16816(o[dp * 2 + 1], ph[kc], vh + 2);
                    mma16816(o[dp * 2],     pl[kc], vh);
                    mma16816(o[dp * 2 + 1], pl[kc], vh + 2);
                    mma16816(o[dp * 2],     ph[kc], vl);
                    mma16816(o[dp * 2 + 1], ph[kc], vl + 2);
                }
            }
        }
    }

    // ---- epilogue: O/l, write [ah|al] proj-A layout ----
    l0 += __shfl_xor_sync(0xffffffffu, l0, 1);
    l0 += __shfl_xor_sync(0xffffffffu, l0, 2);
    l1 += __shfl_xor_sync(0xffffffffu, l1, 1);
    l1 += __shfl_xor_sync(0xffffffffu, l1, 2);
    const float inv0 = 1.f / l0, inv1 = 1.f / l1;

    const int b = bh >> 4, hh = bh & 15;
    const int trow = qw + (lane >> 2);
    const size_t mrow = (size_t)(b * TT + trow);
#pragma unroll
    for (int nt = 0; nt < 8; ++nt) {
        const int d = nt * 8 + 2 * (lane & 3);
        const float v0 = o[nt][0] * inv0, v1 = o[nt][1] * inv0;
        const float v2 = o[nt][2] * inv1, v3 = o[nt][3] * inv1;
        __nv_bfloat16 h0, lo0, h1, lo1;
        split2(v0, h0, lo0); split2(v1, h1, lo1);
        __nv_bfloat16* p0 = g_atts + mrow * K2 + hh * 64 + d;
        *(uint32_t*)p0          = pack2(h0, h1);
        *(uint32_t*)(p0 + 1024) = pack2(lo0, lo1);
        split2(v2, h0, lo0); split2(v3, h1, lo1);
        __nv_bfloat16* p1 = g_atts + (mrow + 8) * K2 + hh * 64 + d;
        *(uint32_t*)p1          = pack2(h0, h1);
        *(uint32_t*)(p1 + 1024) = pack2(lo0, lo1);
    }
}

// ---------------------------------------------------------------------------
extern "C" void kernel_launch(void* const* d_in, const int* in_sizes, int n_in,
                              void* d_out, int out_size)
{
    const float* x  = (const float*)d_in[0];
    // d_in[1] = att_mask (causal tril) — applied analytically
    const float* wq = (const float*)d_in[2];
    const float* bq = (const float*)d_in[3];
    const float* wk = (const float*)d_in[4];
    const float* bk = (const float*)d_in[5];
    const float* wv = (const float*)d_in[6];
    const float* bv = (const float*)d_in[7];
    const float* wp = (const float*)d_in[8];
    const float* bp = (const float*)d_in[9];
    float* out = (float*)d_out;

    __nv_bfloat16 *xs, *wcat, *atts;
    cudaGetSymbolAddress((void**)&xs,   g_xs);
    cudaGetSymbolAddress((void**)&wcat, g_wcat);
    cudaGetSymbolAddress((void**)&atts, g_atts);

    cudaFuncSetAttribute(hmma_gemm<0>, cudaFuncAttributeMaxDynamicSharedMemorySize, GEMM_SMEM);
    cudaFuncSetAttribute(hmma_gemm<1>, cudaFuncAttributeMaxDynamicSharedMemorySize, GEMM_SMEM);
    cudaFuncSetAttribute(attn_kernel,  cudaFuncAttributeMaxDynamicSharedMemorySize, ATT_SMEM);

    // 1) hi/lo splits
    split_x_kernel<<<MTOT, 256>>>(x, xs);
    {
        W4 w;
        w.in[0] = wq; w.in[1] = wk; w.in[2] = wv; w.in[3] = wp;
        dim3 grid(CC, 4);
        split_w4_kernel<<<grid, 256>>>(w);
    }

    // 2) QKV projections (HMMA) -> Q'/K'/V' [h|l] layouts
    {
        GemmP p;
        p.A = xs;
        p.W[0] = wcat + 0 * (size_t)WSZ2; p.bias[0] = bq;
        p.W[1] = wcat + 1 * (size_t)WSZ2; p.bias[1] = bk;
        p.W[2] = wcat + 2 * (size_t)WSZ2; p.bias[2] = bv;
        p.fout = nullptr;
        dim3 grid(CC / 128, MTOT / 128, 3);
        hmma_gemm<1><<<grid, 256, GEMM_SMEM>>>(p);
    }

    // 3) Causal flash attention (HMMA) -> g_atts [ah|al]
    {
        dim3 grid(TT / 128, BB * HH);
        attn_kernel<<<grid, 256, ATT_SMEM>>>();
    }

    // 4) Output projection (HMMA) -> d_out
    {
        GemmP p;
        p.A = atts;
        p.W[0] = wcat + 3 * (size_t)WSZ2; p.bias[0] = bp;
        p.W[1] = p.W[0]; p.bias[1] = bp;
        p.W[2] = p.W[0]; p.bias[2] = bp;
        p.fout = out;
        dim3 grid(CC / 128, MTOT / 128, 1);
        hmma_gemm<0><<<grid, 256, GEMM_SMEM>>>(p);
    }
}

// round 9
// speedup vs baseline: 1.0693x; 1.0693x over previous
#include <cuda_runtime.h>
#include <cuda_bf16.h>
#include <math.h>
#include <stdint.h>

// Problem constants
#define BB 2
#define TT 2048
#define CC 1024
#define HH 16
#define DD 64
#define MTOT 4096
#define K2 2048                // [hi | lo] packed K dimension
#define WSZ2 (CC * K2)

// ---------------------------------------------------------------------------
// Device scratch — all operand tensors stored as unique [hi | lo] halves.
// ---------------------------------------------------------------------------
__device__ __align__(128) __nv_bfloat16 g_xs[(size_t)MTOT * K2];        // x:   [xh | xl]
__device__ __align__(128) __nv_bfloat16 g_wcat[(size_t)4 * WSZ2];       // w*:  [Wh | Wl]
__device__ __align__(128) __nv_bfloat16 g_atts[(size_t)MTOT * K2];      // att: [ah | al]
__device__ __align__(128) __nv_bfloat16 g_qs[(size_t)BB * HH * TT * 128]; // Q' = [Qh|Ql]*0.125
__device__ __align__(128) __nv_bfloat16 g_ks[(size_t)BB * HH * TT * 128]; // K' = [Kh|Kl]
__device__ __align__(128) __nv_bfloat16 g_vs[(size_t)BB * HH * TT * 128]; // V' = [Vh|Vl]

// ---------------------------------------------------------------------------
// PTX helpers (sm_80-class ISA: compiles under compute_103)
// ---------------------------------------------------------------------------
__device__ __forceinline__ uint32_t smem_u32(const void* p) {
    return (uint32_t)__cvta_generic_to_shared(p);
}

__device__ __forceinline__ void cp16(uint32_t dst, const void* src) {
    asm volatile("cp.async.cg.shared.global [%0], [%1], 16;" :: "r"(dst), "l"(src));
}
#define CP_COMMIT() asm volatile("cp.async.commit_group;" ::: "memory")
#define CP_WAIT0()  asm volatile("cp.async.wait_group 0;" ::: "memory")
#define CP_WAIT1()  asm volatile("cp.async.wait_group 1;" ::: "memory")

#define BAR_SYNC(id) asm volatile("bar.sync %0, 128;" :: "r"(id) : "memory")

__device__ __forceinline__ void ldm_x4(uint32_t* r, uint32_t addr) {
    asm volatile("ldmatrix.sync.aligned.m8n8.x4.shared.b16 {%0,%1,%2,%3}, [%4];"
                 : "=r"(r[0]), "=r"(r[1]), "=r"(r[2]), "=r"(r[3]) : "r"(addr));
}
__device__ __forceinline__ void ldm_x4_t(uint32_t* r, uint32_t addr) {
    asm volatile("ldmatrix.sync.aligned.m8n8.x4.trans.shared.b16 {%0,%1,%2,%3}, [%4];"
                 : "=r"(r[0]), "=r"(r[1]), "=r"(r[2]), "=r"(r[3]) : "r"(addr));
}

__device__ __forceinline__ void mma16816(float* c, const uint32_t* a, const uint32_t* b) {
    asm volatile(
        "mma.sync.aligned.m16n8k16.row.col.f32.bf16.bf16.f32 "
        "{%0,%1,%2,%3}, {%4,%5,%6,%7}, {%8,%9}, {%0,%1,%2,%3};"
        : "+f"(c[0]), "+f"(c[1]), "+f"(c[2]), "+f"(c[3])
        : "r"(a[0]), "r"(a[1]), "r"(a[2]), "r"(a[3]), "r"(b[0]), "r"(b[1]));
}

__device__ __forceinline__ uint32_t pack2(__nv_bfloat16 a, __nv_bfloat16 b) {
    union { __nv_bfloat162 v; uint32_t u; } t;
    t.v = __halves2bfloat162(a, b);
    return t.u;
}
__device__ __forceinline__ void split2(float v, __nv_bfloat16& h, __nv_bfloat16& l) {
    h = __float2bfloat16(v);
    l = __float2bfloat16(v - __bfloat162float(h));
}

// ---------------------------------------------------------------------------
// bf16 hi/lo split: out row = [hi(1024) | lo(1024)].
// Products used downstream: h·h' + l·h' + h·l'  == fp32 to ~2^-17.
// ---------------------------------------------------------------------------
__device__ __forceinline__ void split_row(const float* __restrict__ in,
                                          __nv_bfloat16* __restrict__ out,
                                          size_t r, int k)
{
    float4 v = *reinterpret_cast<const float4*>(in + r * CC + k);
    float f[4] = {v.x, v.y, v.z, v.w};
    __nv_bfloat16 hi[4], lo[4];
#pragma unroll
    for (int i = 0; i < 4; i++) split2(f[i], hi[i], lo[i]);
    uint2 hp = make_uint2(pack2(hi[0], hi[1]), pack2(hi[2], hi[3]));
    uint2 lp = make_uint2(pack2(lo[0], lo[1]), pack2(lo[2], lo[3]));
    __nv_bfloat16* o = out + r * K2 + k;
    *reinterpret_cast<uint2*>(o)      = hp;
    *reinterpret_cast<uint2*>(o + CC) = lp;
}

__global__ __launch_bounds__(256) void split_x_kernel(const float* __restrict__ in,
                                                      __nv_bfloat16* __restrict__ out)
{
    split_row(in, out, blockIdx.x, threadIdx.x * 4);
}

struct W4 { const float* in[4]; };
__global__ __launch_bounds__(256) void split_w4_kernel(W4 p)
{
    const int w = blockIdx.y;
    split_row(p.in[w], g_wcat + (size_t)w * WSZ2, blockIdx.x, threadIdx.x * 4);
}

// ---------------------------------------------------------------------------
// HMMA GEMM: out[m,n] = sum_k A[m,k]*W[n,k] + bias[n]  (unchanged from R5)
// ---------------------------------------------------------------------------
struct GemmP {
    const __nv_bfloat16* A;
    const __nv_bfloat16* W[3];
    const float* bias[3];
    float* fout;
};

#define GEMM_NCH 32
#define GEMM_STAGE 32768       // A tile 16KB + W tile 16KB
#define GEMM_SMEM (3 * GEMM_STAGE)

template <int KIND>
__global__ __launch_bounds__(256, 2) void hmma_gemm(GemmP p)
{
    const int z = blockIdx.z;
    const __nv_bfloat16* __restrict__ A = p.A;
    const __nv_bfloat16* __restrict__ W = p.W[z];
    const float* __restrict__ bias = p.bias[z];

    extern __shared__ __align__(1024) char smem[];
    const uint32_t sbase = smem_u32(smem);

    const int m0 = blockIdx.y * 128, n0 = blockIdx.x * 128;
    const int tid = threadIdx.x, lane = tid & 31, wid = tid >> 5;
    const int wm = wid >> 2, wn = wid & 3;

    const __nv_bfloat16* Arow = A + (size_t)m0 * K2;
    const __nv_bfloat16* Wrow = W + (size_t)n0 * K2;

    auto prefetch = [&](int c, int buf) {
        if (c < GEMM_NCH) {
            const uint32_t dst0 = sbase + buf * GEMM_STAGE;
#pragma unroll
            for (int it = 0; it < 8; ++it) {
                const int idx = tid + it * 256;        // 0..2047
                const int mat = idx >> 10;             // 0 = A, 1 = W
                const int rem = idx & 1023;
                const int r = rem >> 3, ch = rem & 7;
                const int col = c * 32 + (ch & 3) * 8 + (ch >> 2) * CC;
                const __nv_bfloat16* src =
                    (mat ? Wrow : Arow) + (size_t)r * K2 + col;
                cp16(dst0 + mat * 16384 + r * 128 + ((uint32_t)(ch ^ (r & 7)) << 4), src);
            }
        }
        CP_COMMIT();
    };

    float acc[4][4][4];
#pragma unroll
    for (int i = 0; i < 4; i++)
#pragma unroll
        for (int j = 0; j < 4; j++)
#pragma unroll
            for (int q = 0; q < 4; q++) acc[i][j][q] = 0.f;

    prefetch(0, 0);
    prefetch(1, 1);

    for (int kc = 0; kc < GEMM_NCH; ++kc) {
        if (kc == GEMM_NCH - 1) { CP_WAIT0(); } else { CP_WAIT1(); }
        __syncthreads();
        prefetch(kc + 2, (kc + 2) % 3);

        const uint32_t bufA = sbase + (kc % 3) * GEMM_STAGE;
        const uint32_t bufW = bufA + 16384;
#pragma unroll
        for (int kk = 0; kk < 2; ++kk) {
            uint32_t ah[4][4], al[4][4];
#pragma unroll
            for (int mt = 0; mt < 4; ++mt) {
                const int r = wm * 64 + mt * 16 + (lane & 15);
                const int ch = kk * 2 + (lane >> 4);
                ldm_x4(ah[mt], bufA + r * 128 + ((uint32_t)(ch ^ (r & 7)) << 4));
                ldm_x4(al[mt], bufA + r * 128 + ((uint32_t)((ch + 4) ^ (r & 7)) << 4));
            }
            uint32_t bh[4][2];
#pragma unroll
            for (int pr = 0; pr < 2; ++pr) {
                const int r = wn * 32 + pr * 16 + (lane & 7) + ((lane >> 4) << 3);
                const int ch = kk * 2 + ((lane >> 3) & 1);
                uint32_t t4[4];
                ldm_x4(t4, bufW + r * 128 + ((uint32_t)(ch ^ (r & 7)) << 4));
                bh[pr * 2][0] = t4[0]; bh[pr * 2][1] = t4[1];
                bh[pr * 2 + 1][0] = t4[2]; bh[pr * 2 + 1][1] = t4[3];
            }
#pragma unroll
            for (int mt = 0; mt < 4; ++mt)
#pragma unroll
                for (int nt = 0; nt < 4; ++nt) {
                    mma16816(acc[mt][nt], ah[mt], bh[nt]);
                    mma16816(acc[mt][nt], al[mt], bh[nt]);
                }
            uint32_t bl[4][2];
#pragma unroll
            for (int pr = 0; pr < 2; ++pr) {
                const int r = wn * 32 + pr * 16 + (lane & 7) + ((lane >> 4) << 3);
                const int ch = kk * 2 + ((lane >> 3) & 1) + 4;
                uint32_t t4[4];
                ldm_x4(t4, bufW + r * 128 + ((uint32_t)(ch ^ (r & 7)) << 4));
                bl[pr * 2][0] = t4[0]; bl[pr * 2][1] = t4[1];
                bl[pr * 2 + 1][0] = t4[2]; bl[pr * 2 + 1][1] = t4[3];
            }
#pragma unroll
            for (int mt = 0; mt < 4; ++mt)
#pragma unroll
                for (int nt = 0; nt < 4; ++nt)
                    mma16816(acc[mt][nt], ah[mt], bl[nt]);
        }
    }

    // Epilogue
    const int r0g = m0 + wm * 64 + (lane >> 2);
    const int nbase = n0 + wn * 32 + 2 * (lane & 3);
#pragma unroll
    for (int mt = 0; mt < 4; ++mt) {
        const int m = r0g + mt * 16;
#pragma unroll
        for (int nt = 0; nt < 4; ++nt) {
            const int n = nbase + nt * 8;
            float v0 = acc[mt][nt][0] + bias[n];
            float v1 = acc[mt][nt][1] + bias[n + 1];
            float v2 = acc[mt][nt][2] + bias[n];
            float v3 = acc[mt][nt][3] + bias[n + 1];
            if (KIND == 0) {
                *reinterpret_cast<float2*>(p.fout + (size_t)m * CC + n) = make_float2(v0, v1);
                *reinterpret_cast<float2*>(p.fout + (size_t)(m + 8) * CC + n) = make_float2(v2, v3);
            } else {
                if (z == 0) { v0 *= 0.125f; v1 *= 0.125f; v2 *= 0.125f; v3 *= 0.125f; }
                __nv_bfloat16* target = (z == 0) ? g_qs : (z == 1) ? g_ks : g_vs;
                const int hh = n >> 6, d = n & 63;
#pragma unroll
                for (int rr = 0; rr < 2; ++rr) {
                    const int mm = m + rr * 8;
                    const float a0 = rr ? v2 : v0, a1 = rr ? v3 : v1;
                    const int b = mm >> 11, t = mm & (TT - 1);
                    const size_t row = ((size_t)(b * HH + hh)) * TT + t;
                    __nv_bfloat16 h0, l0, h1, l1;
                    split2(a0, h0, l0);
                    split2(a1, h1, l1);
                    __nv_bfloat16* q = target + row * 128 + d;
                    *(uint32_t*)q        = pack2(h0, h1);
                    *(uint32_t*)(q + 64) = pack2(l0, l1);
                }
            }
        }
    }
}

// ---------------------------------------------------------------------------
// Flash attention on HMMA — intra-CTA split-KV warp-group ping-pong.
// CTA: 64 q rows, 8 warps. Group g = warps [4g..4g+3] processes KV blocks of
// parity g with its OWN 2-stage smem ring + named barrier — no CTA barrier in
// the main loop, so the two groups drift out of phase and fill each other's
// tensor-pipe bubbles (softmax phase of one overlaps MMA phase of the other).
// Each group keeps private (m,l,O); merged exactly at the end via smem.
// S = Qh*Kh + Ql*Kh + Qh*Kl (scale pre-folded). P split-2 -> PV with Vh/Vl.
// ---------------------------------------------------------------------------
#define ATT_STAGE 32768                  // Kh|Kl|Vh|Vl tiles of 8KB (64 kv rows)
#define ATT_GRP   (2 * ATT_STAGE)        // per-group ring: 64KB
#define ATT_SMEM  (2 * ATT_GRP)          // 128KB

__global__ __launch_bounds__(256, 1) void attn_kernel()
{
    extern __shared__ __align__(1024) char smem[];
    const uint32_t sbase = smem_u32(smem);

    const int bh = blockIdx.y;
    const int qb = (int)gridDim.x - 1 - (int)blockIdx.x;  // reversed for balance
    const int q0 = qb * 64;
    const int tid = threadIdx.x, lane = tid & 31, wid = tid >> 5;
    const int grp = wid >> 2;                  // 0 or 1
    const int gtid = tid & 127;
    const int qw = q0 + (wid & 3) * 16;        // warp's 16 q rows
    const uint32_t grp_base = sbase + grp * ATT_GRP;

    // Q' fragments (persist in regs): 4 d16-chunks, hi and lo
    uint32_t aqh[4][4], aql[4][4];
    {
        const uint32_t* q32 = reinterpret_cast<const uint32_t*>(g_qs) + (size_t)bh * TT * 64;
        const uint32_t* r0p = q32 + (size_t)(qw + (lane >> 2)) * 64;
        const uint32_t* r1p = r0p + 8 * 64;
        const int c0 = lane & 3;
#pragma unroll
        for (int k = 0; k < 4; ++k) {
            aqh[k][0] = r0p[k * 8 + c0];
            aqh[k][1] = r1p[k * 8 + c0];
            aqh[k][2] = r0p[k * 8 + 4 + c0];
            aqh[k][3] = r1p[k * 8 + 4 + c0];
            aql[k][0] = r0p[32 + k * 8 + c0];
            aql[k][1] = r1p[32 + k * 8 + c0];
            aql[k][2] = r0p[32 + k * 8 + 4 + c0];
            aql[k][3] = r1p[32 + k * 8 + 4 + c0];
        }
    }

    float o[8][4];
#pragma unroll
    for (int i = 0; i < 8; i++)
#pragma unroll
        for (int j = 0; j < 4; j++) o[i][j] = 0.f;
    float m0r = -INFINITY, m1r = -INFINITY, l0 = 0.f, l1 = 0.f;

    const char* ksrc_base = reinterpret_cast<const char*>(g_ks) + (size_t)bh * TT * 256;
    const char* vsrc_base = reinterpret_cast<const char*>(g_vs) + (size_t)bh * TT * 256;

    auto prefetchKV = [&](int kb, int stg) {
        const uint32_t dst = grp_base + stg * ATT_STAGE;
        const char* ks = ksrc_base + (size_t)kb * 64 * 256;
        const char* vs = vsrc_base + (size_t)kb * 64 * 256;
#pragma unroll
        for (int it = 0; it < 16; ++it) {
            const int idx = gtid + it * 128;       // 0..2047
            const int mat = idx >> 10;             // 0 = K, 1 = V
            const int rem = idx & 1023;
            const int sub = rem >> 9;              // 0 = hi, 1 = lo
            const int r = (rem >> 3) & 63;
            const int ch = rem & 7;
            const char* src = (mat ? vs : ks) + (size_t)r * 256 + sub * 128 + ch * 16;
            cp16(dst + mat * 16384 + sub * 8192 + r * 128 +
                     ((uint32_t)(ch ^ (r & 7)) << 4), src);
        }
        CP_COMMIT();
    };

    // Group g handles blocks {g, g+2, ...} within [0, qb].
    int stg = 0;
    if (grp <= qb) prefetchKV(grp, 0);

    for (int kb = grp; kb <= qb; kb += 2) {
        CP_WAIT0();
        BAR_SYNC(4 + grp);                       // group-local barrier
        if (kb + 2 <= qb) prefetchKV(kb + 2, stg ^ 1);
        const int kv0 = kb * 64;

        const uint32_t Kh = grp_base + stg * ATT_STAGE;
        const uint32_t Kl = Kh + 8192;
        const uint32_t Vh = Kh + 16384;
        const uint32_t Vl = Kh + 24576;
        stg ^= 1;

        // ---- S = Qh*Kh + Ql*Kh + Qh*Kl ----
        float s[8][4];
#pragma unroll
        for (int i = 0; i < 8; i++)
#pragma unroll
            for (int j = 0; j < 4; j++) s[i][j] = 0.f;
#pragma unroll
        for (int d16 = 0; d16 < 4; ++d16) {
#pragma unroll
            for (int pr = 0; pr < 4; ++pr) {
                const int r = pr * 16 + (lane & 7) + ((lane >> 4) << 3);
                const int ch = d16 * 2 + ((lane >> 3) & 1);
                const uint32_t sw = (uint32_t)(ch ^ (r & 7)) << 4;
                uint32_t kh4[4];
                ldm_x4(kh4, Kh + r * 128 + sw);
                mma16816(s[pr * 2],     aqh[d16], kh4);
                mma16816(s[pr * 2 + 1], aqh[d16], kh4 + 2);
                mma16816(s[pr * 2],     aql[d16], kh4);
                mma16816(s[pr * 2 + 1], aql[d16], kh4 + 2);
                uint32_t kl4[4];
                ldm_x4(kl4, Kl + r * 128 + sw);
                mma16816(s[pr * 2],     aqh[d16], kl4);
                mma16816(s[pr * 2 + 1], aqh[d16], kl4 + 2);
            }
        }

        const int r0 = qw + (lane >> 2), r1 = r0 + 8;
        if (kv0 + 63 > qw) {  // causal mask region
#pragma unroll
            for (int nt = 0; nt < 8; ++nt) {
                const int j = kv0 + nt * 8 + 2 * (lane & 3);
                if (j > r0)     s[nt][0] = -INFINITY;
                if (j + 1 > r0) s[nt][1] = -INFINITY;
                if (j > r1)     s[nt][2] = -INFINITY;
                if (j + 1 > r1) s[nt][3] = -INFINITY;
            }
        }

        // ---- online softmax ----
        float b0 = -INFINITY, b1 = -INFINITY;
#pragma unroll
        for (int nt = 0; nt < 8; ++nt) {
            b0 = fmaxf(b0, fmaxf(s[nt][0], s[nt][1]));
            b1 = fmaxf(b1, fmaxf(s[nt][2], s[nt][3]));
        }
        b0 = fmaxf(b0, __shfl_xor_sync(0xffffffffu, b0, 1));
        b0 = fmaxf(b0, __shfl_xor_sync(0xffffffffu, b0, 2));
        b1 = fmaxf(b1, __shfl_xor_sync(0xffffffffu, b1, 1));
        b1 = fmaxf(b1, __shfl_xor_sync(0xffffffffu, b1, 2));
        const float mn0 = fmaxf(m0r, b0), mn1 = fmaxf(m1r, b1);
        const float cor0 = __expf(m0r - mn0), cor1 = __expf(m1r - mn1);
        m0r = mn0; m1r = mn1;
        l0 *= cor0; l1 *= cor1;
#pragma unroll
        for (int nt = 0; nt < 8; ++nt) {
            o[nt][0] *= cor0; o[nt][1] *= cor0;
            o[nt][2] *= cor1; o[nt][3] *= cor1;
        }

        // ---- P = exp(S - m), split-2, repack C-frag -> A-frag ----
        uint32_t ph[4][4], pl[4][4];
#pragma unroll
        for (int kc = 0; kc < 4; ++kc) {
#pragma unroll
            for (int half = 0; half < 2; ++half) {
                const int nt = kc * 2 + half;
                const float p0 = __expf(s[nt][0] - mn0);
                const float p1 = __expf(s[nt][1] - mn0);
                const float p2 = __expf(s[nt][2] - mn1);
                const float p3 = __expf(s[nt][3] - mn1);
                l0 += p0 + p1; l1 += p2 + p3;
                __nv_bfloat16 h0, lo0, h1, lo1, h2, lo2, h3, lo3;
                split2(p0, h0, lo0); split2(p1, h1, lo1);
                split2(p2, h2, lo2); split2(p3, h3, lo3);
                ph[kc][half * 2]     = pack2(h0, h1);
                ph[kc][half * 2 + 1] = pack2(h2, h3);
                pl[kc][half * 2]     = pack2(lo0, lo1);
                pl[kc][half * 2 + 1] = pack2(lo2, lo3);
            }
        }

        // ---- O += Ph*Vh + Pl*Vh + Ph*Vl ----
#pragma unroll
        for (int kc = 0; kc < 4; ++kc) {
            const int r = kc * 16 + (lane & 7) + ((lane >> 3) & 1) * 8;
#pragma unroll
            for (int dp = 0; dp < 4; ++dp) {
                const int ch = dp * 2 + (lane >> 4);
                const uint32_t sw = (uint32_t)(ch ^ (r & 7)) << 4;
                uint32_t vh[4], vl[4];
                ldm_x4_t(vh, Vh + r * 128 + sw);
                ldm_x4_t(vl, Vl + r * 128 + sw);
                mma16816(o[dp * 2],     ph[kc], vh);
                mma16816(o[dp * 2 + 1], ph[kc], vh + 2);
                mma16816(o[dp * 2],     pl[kc], vh);
                mma16816(o[dp * 2 + 1], pl[kc], vh + 2);
                mma16816(o[dp * 2],     ph[kc], vl);
                mma16816(o[dp * 2 + 1], ph[kc], vl + 2);
            }
        }
    }

    // ---- merge the two groups' partial softmax states ----
    // Group 1 publishes (m0,m1,l0,l1,o[32]) to its own (now idle) smem ring.
    float* xch = reinterpret_cast<float*>(smem + ATT_GRP) + (size_t)gtid * 37;
    if (grp == 1) {
        xch[0] = m0r; xch[1] = m1r; xch[2] = l0; xch[3] = l1;
#pragma unroll
        for (int nt = 0; nt < 8; ++nt) {
            xch[4 + nt * 4 + 0] = o[nt][0];
            xch[4 + nt * 4 + 1] = o[nt][1];
            xch[4 + nt * 4 + 2] = o[nt][2];
            xch[4 + nt * 4 + 3] = o[nt][3];
        }
    }
    __syncthreads();
    if (grp == 1) return;

    {
        const float mb0 = xch[0], mb1 = xch[1];
        const float lb0 = xch[2], lb1 = xch[3];
        const float mn0 = fmaxf(m0r, mb0), mn1 = fmaxf(m1r, mb1);
        const float ca0 = __expf(m0r - mn0), cb0 = __expf(mb0 - mn0);
        const float ca1 = __expf(m1r - mn1), cb1 = __expf(mb1 - mn1);
        l0 = l0 * ca0 + lb0 * cb0;
        l1 = l1 * ca1 + lb1 * cb1;
#pragma unroll
        for (int nt = 0; nt < 8; ++nt) {
            o[nt][0] = o[nt][0] * ca0 + xch[4 + nt * 4 + 0] * cb0;
            o[nt][1] = o[nt][1] * ca0 + xch[4 + nt * 4 + 1] * cb0;
            o[nt][2] = o[nt][2] * ca1 + xch[4 + nt * 4 + 2] * cb1;
            o[nt][3] = o[nt][3] * ca1 + xch[4 + nt * 4 + 3] * cb1;
        }
    }

    // ---- epilogue: O/l, write [ah|al] proj-A layout ----
    l0 += __shfl_xor_sync(0xffffffffu, l0, 1);
    l0 += __shfl_xor_sync(0xffffffffu, l0, 2);
    l1 += __shfl_xor_sync(0xffffffffu, l1, 1);
    l1 += __shfl_xor_sync(0xffffffffu, l1, 2);
    const float inv0 = 1.f / l0, inv1 = 1.f / l1;

    const int b = bh >> 4, hh = bh & 15;
    const int trow = qw + (lane >> 2);
    const size_t mrow = (size_t)(b * TT + trow);
#pragma unroll
    for (int nt = 0; nt < 8; ++nt) {
        const int d = nt * 8 + 2 * (lane & 3);
        const float v0 = o[nt][0] * inv0, v1 = o[nt][1] * inv0;
        const float v2 = o[nt][2] * inv1, v3 = o[nt][3] * inv1;
        __nv_bfloat16 h0, lo0, h1, lo1;
        split2(v0, h0, lo0); split2(v1, h1, lo1);
        __nv_bfloat16* p0 = g_atts + mrow * K2 + hh * 64 + d;
        *(uint32_t*)p0          = pack2(h0, h1);
        *(uint32_t*)(p0 + 1024) = pack2(lo0, lo1);
        split2(v2, h0, lo0); split2(v3, h1, lo1);
        __nv_bfloat16* p1 = g_atts + (mrow + 8) * K2 + hh * 64 + d;
        *(uint32_t*)p1          = pack2(h0, h1);
        *(uint32_t*)(p1 + 1024) = pack2(lo0, lo1);
    }
}

// ---------------------------------------------------------------------------
extern "C" void kernel_launch(void* const* d_in, const int* in_sizes, int n_in,
                              void* d_out, int out_size)
{
    const float* x  = (const float*)d_in[0];
    // d_in[1] = att_mask (causal tril) — applied analytically
    const float* wq = (const float*)d_in[2];
    const float* bq = (const float*)d_in[3];
    const float* wk = (const float*)d_in[4];
    const float* bk = (const float*)d_in[5];
    const float* wv = (const float*)d_in[6];
    const float* bv = (const float*)d_in[7];
    const float* wp = (const float*)d_in[8];
    const float* bp = (const float*)d_in[9];
    float* out = (float*)d_out;

    __nv_bfloat16 *xs, *wcat, *atts;
    cudaGetSymbolAddress((void**)&xs,   g_xs);
    cudaGetSymbolAddress((void**)&wcat, g_wcat);
    cudaGetSymbolAddress((void**)&atts, g_atts);

    cudaFuncSetAttribute(hmma_gemm<0>, cudaFuncAttributeMaxDynamicSharedMemorySize, GEMM_SMEM);
    cudaFuncSetAttribute(hmma_gemm<1>, cudaFuncAttributeMaxDynamicSharedMemorySize, GEMM_SMEM);
    cudaFuncSetAttribute(attn_kernel,  cudaFuncAttributeMaxDynamicSharedMemorySize, ATT_SMEM);

    // 1) hi/lo splits
    split_x_kernel<<<MTOT, 256>>>(x, xs);
    {
        W4 w;
        w.in[0] = wq; w.in[1] = wk; w.in[2] = wv; w.in[3] = wp;
        dim3 grid(CC, 4);
        split_w4_kernel<<<grid, 256>>>(w);
    }

    // 2) QKV projections (HMMA) -> Q'/K'/V' [h|l] layouts
    {
        GemmP p;
        p.A = xs;
        p.W[0] = wcat + 0 * (size_t)WSZ2; p.bias[0] = bq;
        p.W[1] = wcat + 1 * (size_t)WSZ2; p.bias[1] = bk;
        p.W[2] = wcat + 2 * (size_t)WSZ2; p.bias[2] = bv;
        p.fout = nullptr;
        dim3 grid(CC / 128, MTOT / 128, 3);
        hmma_gemm<1><<<grid, 256, GEMM_SMEM>>>(p);
    }

    // 3) Causal flash attention (HMMA, split-KV warp groups) -> g_atts [ah|al]
    {
        dim3 grid(TT / 64, BB * HH);
        attn_kernel<<<grid, 256, ATT_SMEM>>>();
    }

    // 4) Output projection (HMMA) -> d_out
    {
        GemmP p;
        p.A = atts;
        p.W[0] = wcat + 3 * (size_t)WSZ2; p.bias[0] = bp;
        p.W[1] = p.W[0]; p.bias[1] = bp;
        p.W[2] = p.W[0]; p.bias[2] = bp;
        p.fout = out;
        dim3 grid(CC / 128, MTOT / 128, 1);
        hmma_gemm<0><<<grid, 256, GEMM_SMEM>>>(p);
    }
}

// round 13
// speedup vs baseline: 1.0971x; 1.0259x over previous
#include <cuda_runtime.h>
#include <cuda_bf16.h>
#include <math.h>
#include <stdint.h>

// Problem constants
#define BB 2
#define TT 2048
#define CC 1024
#define HH 16
#define DD 64
#define MTOT 4096
#define K2 2048                // [hi | lo] packed K dimension
#define WSZ2 (CC * K2)

// ---------------------------------------------------------------------------
// Device scratch — all operand tensors stored as unique [hi | lo] halves.
// ---------------------------------------------------------------------------
__device__ __align__(128) __nv_bfloat16 g_xs[(size_t)MTOT * K2];        // x:   [xh | xl]
__device__ __align__(128) __nv_bfloat16 g_wcat[(size_t)4 * WSZ2];       // w*:  [Wh | Wl]
__device__ __align__(128) __nv_bfloat16 g_atts[(size_t)MTOT * K2];      // att: [ah | al]
__device__ __align__(128) __nv_bfloat16 g_qs[(size_t)BB * HH * TT * 128]; // Q' = [Qh|Ql]*0.125
__device__ __align__(128) __nv_bfloat16 g_ks[(size_t)BB * HH * TT * 128]; // K' = [Kh|Kl]
__device__ __align__(128) __nv_bfloat16 g_vs[(size_t)BB * HH * TT * 128]; // V' = [Vh|Vl]

// ---------------------------------------------------------------------------
// PTX helpers (sm_80-class ISA: compiles under compute_103)
// ---------------------------------------------------------------------------
__device__ __forceinline__ uint32_t smem_u32(const void* p) {
    return (uint32_t)__cvta_generic_to_shared(p);
}

__device__ __forceinline__ void cp16(uint32_t dst, const void* src) {
    asm volatile("cp.async.cg.shared.global [%0], [%1], 16;" :: "r"(dst), "l"(src));
}
#define CP_COMMIT() asm volatile("cp.async.commit_group;" ::: "memory")
#define CP_WAIT0()  asm volatile("cp.async.wait_group 0;" ::: "memory")
#define CP_WAIT1()  asm volatile("cp.async.wait_group 1;" ::: "memory")
#define CP_WAIT2()  asm volatile("cp.async.wait_group 2;" ::: "memory")

#define BAR_SYNC(id) asm volatile("bar.sync %0, 128;" :: "r"(id) : "memory")

__device__ __forceinline__ void ldm_x4(uint32_t* r, uint32_t addr) {
    asm volatile("ldmatrix.sync.aligned.m8n8.x4.shared.b16 {%0,%1,%2,%3}, [%4];"
                 : "=r"(r[0]), "=r"(r[1]), "=r"(r[2]), "=r"(r[3]) : "r"(addr));
}
__device__ __forceinline__ void ldm_x4_t(uint32_t* r, uint32_t addr) {
    asm volatile("ldmatrix.sync.aligned.m8n8.x4.trans.shared.b16 {%0,%1,%2,%3}, [%4];"
                 : "=r"(r[0]), "=r"(r[1]), "=r"(r[2]), "=r"(r[3]) : "r"(addr));
}

__device__ __forceinline__ void mma16816(float* c, const uint32_t* a, const uint32_t* b) {
    asm volatile(
        "mma.sync.aligned.m16n8k16.row.col.f32.bf16.bf16.f32 "
        "{%0,%1,%2,%3}, {%4,%5,%6,%7}, {%8,%9}, {%0,%1,%2,%3};"
        : "+f"(c[0]), "+f"(c[1]), "+f"(c[2]), "+f"(c[3])
        : "r"(a[0]), "r"(a[1]), "r"(a[2]), "r"(a[3]), "r"(b[0]), "r"(b[1]));
}

__device__ __forceinline__ uint32_t pack2(__nv_bfloat16 a, __nv_bfloat16 b) {
    union { __nv_bfloat162 v; uint32_t u; } t;
    t.v = __halves2bfloat162(a, b);
    return t.u;
}
__device__ __forceinline__ void split2(float v, __nv_bfloat16& h, __nv_bfloat16& l) {
    h = __float2bfloat16(v);
    l = __float2bfloat16(v - __bfloat162float(h));
}

// ---------------------------------------------------------------------------
// bf16 hi/lo split: out row = [hi(1024) | lo(1024)].
// ---------------------------------------------------------------------------
__device__ __forceinline__ void split_row(const float* __restrict__ in,
                                          __nv_bfloat16* __restrict__ out,
                                          size_t r, int k)
{
    float4 v = *reinterpret_cast<const float4*>(in + r * CC + k);
    float f[4] = {v.x, v.y, v.z, v.w};
    __nv_bfloat16 hi[4], lo[4];
#pragma unroll
    for (int i = 0; i < 4; i++) split2(f[i], hi[i], lo[i]);
    uint2 hp = make_uint2(pack2(hi[0], hi[1]), pack2(hi[2], hi[3]));
    uint2 lp = make_uint2(pack2(lo[0], lo[1]), pack2(lo[2], lo[3]));
    __nv_bfloat16* o = out + r * K2 + k;
    *reinterpret_cast<uint2*>(o)      = hp;
    *reinterpret_cast<uint2*>(o + CC) = lp;
}

__global__ __launch_bounds__(256) void split_x_kernel(const float* __restrict__ in,
                                                      __nv_bfloat16* __restrict__ out)
{
    split_row(in, out, blockIdx.x, threadIdx.x * 4);
}

struct W4 { const float* in[4]; };
__global__ __launch_bounds__(256) void split_w4_kernel(W4 p)
{
    const int w = blockIdx.y;
    split_row(p.in[w], g_wcat + (size_t)w * WSZ2, blockIdx.x, threadIdx.x * 4);
}

// ---------------------------------------------------------------------------
// HMMA GEMM: out[m,n] = sum_k A[m,k]*W[n,k] + bias[n]
// kk body resequenced to cut peak live registers (no spills under 128 cap):
//   bh -> ah*bh (16), bl -> ah*bl (16), al -> al*bh (16). Peak ~96 regs.
// ---------------------------------------------------------------------------
struct GemmP {
    const __nv_bfloat16* A;
    const __nv_bfloat16* W[3];
    const float* bias[3];
    float* fout;
};

#define GEMM_NCH 32
#define GEMM_STAGE 32768       // A tile 16KB + W tile 16KB
#define GEMM_SMEM (3 * GEMM_STAGE)

template <int KIND>
__global__ __launch_bounds__(256, 2) void hmma_gemm(GemmP p)
{
    const int z = blockIdx.z;
    const __nv_bfloat16* __restrict__ A = p.A;
    const __nv_bfloat16* __restrict__ W = p.W[z];
    const float* __restrict__ bias = p.bias[z];

    extern __shared__ __align__(1024) char smem[];
    const uint32_t sbase = smem_u32(smem);

    const int m0 = blockIdx.y * 128, n0 = blockIdx.x * 128;
    const int tid = threadIdx.x, lane = tid & 31, wid = tid >> 5;
    const int wm = wid >> 2, wn = wid & 3;

    const __nv_bfloat16* Arow = A + (size_t)m0 * K2;
    const __nv_bfloat16* Wrow = W + (size_t)n0 * K2;

    auto prefetch = [&](int c, int buf) {
        if (c < GEMM_NCH) {
            const uint32_t dst0 = sbase + buf * GEMM_STAGE;
#pragma unroll
            for (int it = 0; it < 8; ++it) {
                const int idx = tid + it * 256;        // 0..2047
                const int mat = idx >> 10;             // 0 = A, 1 = W
                const int rem = idx & 1023;
                const int r = rem >> 3, ch = rem & 7;
                const int col = c * 32 + (ch & 3) * 8 + (ch >> 2) * CC;
                const __nv_bfloat16* src =
                    (mat ? Wrow : Arow) + (size_t)r * K2 + col;
                cp16(dst0 + mat * 16384 + r * 128 + ((uint32_t)(ch ^ (r & 7)) << 4), src);
            }
        }
        CP_COMMIT();
    };

    float acc[4][4][4];
#pragma unroll
    for (int i = 0; i < 4; i++)
#pragma unroll
        for (int j = 0; j < 4; j++)
#pragma unroll
            for (int q = 0; q < 4; q++) acc[i][j][q] = 0.f;

    prefetch(0, 0);
    prefetch(1, 1);

    for (int kc = 0; kc < GEMM_NCH; ++kc) {
        if (kc == GEMM_NCH - 1) { CP_WAIT0(); } else { CP_WAIT1(); }
        __syncthreads();
        prefetch(kc + 2, (kc + 2) % 3);

        const uint32_t bufA = sbase + (kc % 3) * GEMM_STAGE;
        const uint32_t bufW = bufA + 16384;
#pragma unroll
        for (int kk = 0; kk < 2; ++kk) {
            // W hi fragments
            uint32_t bh[4][2];
#pragma unroll
            for (int pr = 0; pr < 2; ++pr) {
                const int r = wn * 32 + pr * 16 + (lane & 7) + ((lane >> 4) << 3);
                const int ch = kk * 2 + ((lane >> 3) & 1);
                uint32_t t4[4];
                ldm_x4(t4, bufW + r * 128 + ((uint32_t)(ch ^ (r & 7)) << 4));
                bh[pr * 2][0] = t4[0]; bh[pr * 2][1] = t4[1];
                bh[pr * 2 + 1][0] = t4[2]; bh[pr * 2 + 1][1] = t4[3];
            }
            // A hi fragments; ah*bh
            uint32_t ah[4][4];
#pragma unroll
            for (int mt = 0; mt < 4; ++mt) {
                const int r = wm * 64 + mt * 16 + (lane & 15);
                const int ch = kk * 2 + (lane >> 4);
                ldm_x4(ah[mt], bufA + r * 128 + ((uint32_t)(ch ^ (r & 7)) << 4));
            }
#pragma unroll
            for (int mt = 0; mt < 4; ++mt)
#pragma unroll
                for (int nt = 0; nt < 4; ++nt)
                    mma16816(acc[mt][nt], ah[mt], bh[nt]);
            // W lo fragments; ah*bl (ah dies after)
            {
                uint32_t bl[4][2];
#pragma unroll
                for (int pr = 0; pr < 2; ++pr) {
                    const int r = wn * 32 + pr * 16 + (lane & 7) + ((lane >> 4) << 3);
                    const int ch = kk * 2 + ((lane >> 3) & 1) + 4;
                    uint32_t t4[4];
                    ldm_x4(t4, bufW + r * 128 + ((uint32_t)(ch ^ (r & 7)) << 4));
                    bl[pr * 2][0] = t4[0]; bl[pr * 2][1] = t4[1];
                    bl[pr * 2 + 1][0] = t4[2]; bl[pr * 2 + 1][1] = t4[3];
                }
#pragma unroll
                for (int mt = 0; mt < 4; ++mt)
#pragma unroll
                    for (int nt = 0; nt < 4; ++nt)
                        mma16816(acc[mt][nt], ah[mt], bl[nt]);
            }
            // A lo fragments; al*bh
            {
                uint32_t al[4][4];
#pragma unroll
                for (int mt = 0; mt < 4; ++mt) {
                    const int r = wm * 64 + mt * 16 + (lane & 15);
                    const int ch = kk * 2 + (lane >> 4);
                    ldm_x4(al[mt], bufA + r * 128 + ((uint32_t)((ch + 4) ^ (r & 7)) << 4));
                }
#pragma unroll
                for (int mt = 0; mt < 4; ++mt)
#pragma unroll
                    for (int nt = 0; nt < 4; ++nt)
                        mma16816(acc[mt][nt], al[mt], bh[nt]);
            }
        }
    }

    // Epilogue
    const int r0g = m0 + wm * 64 + (lane >> 2);
    const int nbase = n0 + wn * 32 + 2 * (lane & 3);
#pragma unroll
    for (int mt = 0; mt < 4; ++mt) {
        const int m = r0g + mt * 16;
#pragma unroll
        for (int nt = 0; nt < 4; ++nt) {
            const int n = nbase + nt * 8;
            float v0 = acc[mt][nt][0] + bias[n];
            float v1 = acc[mt][nt][1] + bias[n + 1];
            float v2 = acc[mt][nt][2] + bias[n];
            float v3 = acc[mt][nt][3] + bias[n + 1];
            if (KIND == 0) {
                *reinterpret_cast<float2*>(p.fout + (size_t)m * CC + n) = make_float2(v0, v1);
                *reinterpret_cast<float2*>(p.fout + (size_t)(m + 8) * CC + n) = make_float2(v2, v3);
            } else {
                if (z == 0) { v0 *= 0.125f; v1 *= 0.125f; v2 *= 0.125f; v3 *= 0.125f; }
                __nv_bfloat16* target = (z == 0) ? g_qs : (z == 1) ? g_ks : g_vs;
                const int hh = n >> 6, d = n & 63;
#pragma unroll
                for (int rr = 0; rr < 2; ++rr) {
                    const int mm = m + rr * 8;
                    const float a0 = rr ? v2 : v0, a1 = rr ? v3 : v1;
                    const int b = mm >> 11, t = mm & (TT - 1);
                    const size_t row = ((size_t)(b * HH + hh)) * TT + t;
                    __nv_bfloat16 h0, l0, h1, l1;
                    split2(a0, h0, l0);
                    split2(a1, h1, l1);
                    __nv_bfloat16* q = target + row * 128 + d;
                    *(uint32_t*)q        = pack2(h0, h1);
                    *(uint32_t*)(q + 64) = pack2(l0, l1);
                }
            }
        }
    }
}

// ---------------------------------------------------------------------------
// Flash attention — split-KV warp-group ping-pong + per-warp software
// pipelining. CTA: 64 q rows, 2 groups of 4 warps; group g handles KV blocks
// of parity g with a private 3-stage ring and named barrier. Inside each
// iteration, S(kb+2) MMAs (independent) are emitted alongside the
// softmax(kb)+PV(kb) chain so the scheduler fills tensor-pipe bubbles.
// ---------------------------------------------------------------------------
#define ATT_STAGE 32768                  // Kh|Kl|Vh|Vl tiles of 8KB (64 kv rows)
#define ATT_GRP   (3 * ATT_STAGE)        // per-group ring: 96KB
#define ATT_SMEM  (2 * ATT_GRP)          // 192KB

__device__ __forceinline__ void compute_S(
    float (&s)[8][4], uint32_t Kh,
    const uint32_t (&aqh)[4][4], const uint32_t (&aql)[4][4], int lane)
{
    const uint32_t Kl = Kh + 8192;
#pragma unroll
    for (int i = 0; i < 8; i++)
#pragma unroll
        for (int j = 0; j < 4; j++) s[i][j] = 0.f;
#pragma unroll
    for (int d16 = 0; d16 < 4; ++d16) {
#pragma unroll
        for (int pr = 0; pr < 4; ++pr) {
            const int r = pr * 16 + (lane & 7) + ((lane >> 4) << 3);
            const int ch = d16 * 2 + ((lane >> 3) & 1);
            const uint32_t sw = (uint32_t)(ch ^ (r & 7)) << 4;
            uint32_t kh4[4];
            ldm_x4(kh4, Kh + r * 128 + sw);
            mma16816(s[pr * 2],     aqh[d16], kh4);
            mma16816(s[pr * 2 + 1], aqh[d16], kh4 + 2);
            mma16816(s[pr * 2],     aql[d16], kh4);
            mma16816(s[pr * 2 + 1], aql[d16], kh4 + 2);
            uint32_t kl4[4];
            ldm_x4(kl4, Kl + r * 128 + sw);
            mma16816(s[pr * 2],     aqh[d16], kl4);
            mma16816(s[pr * 2 + 1], aqh[d16], kl4 + 2);
        }
    }
}

__device__ __forceinline__ void softmax_pv(
    float (&s)[8][4], uint32_t Kbase, int kv0, int qw, int lane,
    float (&o)[8][4], float& m0r, float& m1r, float& l0, float& l1)
{
    const uint32_t Vh = Kbase + 16384, Vl = Kbase + 24576;
    const int r0 = qw + (lane >> 2), r1 = r0 + 8;
    if (kv0 + 63 > qw) {  // causal mask (diagonal block only)
#pragma unroll
        for (int nt = 0; nt < 8; ++nt) {
            const int j = kv0 + nt * 8 + 2 * (lane & 3);
            if (j > r0)     s[nt][0] = -INFINITY;
            if (j + 1 > r0) s[nt][1] = -INFINITY;
            if (j > r1)     s[nt][2] = -INFINITY;
            if (j + 1 > r1) s[nt][3] = -INFINITY;
        }
    }

    float b0 = -INFINITY, b1 = -INFINITY;
#pragma unroll
    for (int nt = 0; nt < 8; ++nt) {
        b0 = fmaxf(b0, fmaxf(s[nt][0], s[nt][1]));
        b1 = fmaxf(b1, fmaxf(s[nt][2], s[nt][3]));
    }
    b0 = fmaxf(b0, __shfl_xor_sync(0xffffffffu, b0, 1));
    b0 = fmaxf(b0, __shfl_xor_sync(0xffffffffu, b0, 2));
    b1 = fmaxf(b1, __shfl_xor_sync(0xffffffffu, b1, 1));
    b1 = fmaxf(b1, __shfl_xor_sync(0xffffffffu, b1, 2));
    const float mn0 = fmaxf(m0r, b0), mn1 = fmaxf(m1r, b1);
    const float cor0 = __expf(m0r - mn0), cor1 = __expf(m1r - mn1);
    m0r = mn0; m1r = mn1;
    l0 *= cor0; l1 *= cor1;
#pragma unroll
    for (int nt = 0; nt < 8; ++nt) {
        o[nt][0] *= cor0; o[nt][1] *= cor0;
        o[nt][2] *= cor1; o[nt][3] *= cor1;
    }

    uint32_t ph[4][4], pl[4][4];
#pragma unroll
    for (int kc = 0; kc < 4; ++kc) {
#pragma unroll
        for (int half = 0; half < 2; ++half) {
            const int nt = kc * 2 + half;
            const float p0 = __expf(s[nt][0] - mn0);
            const float p1 = __expf(s[nt][1] - mn0);
            const float p2 = __expf(s[nt][2] - mn1);
            const float p3 = __expf(s[nt][3] - mn1);
            l0 += p0 + p1; l1 += p2 + p3;
            __nv_bfloat16 h0, lo0, h1, lo1, h2, lo2, h3, lo3;
            split2(p0, h0, lo0); split2(p1, h1, lo1);
            split2(p2, h2, lo2); split2(p3, h3, lo3);
            ph[kc][half * 2]     = pack2(h0, h1);
            ph[kc][half * 2 + 1] = pack2(h2, h3);
            pl[kc][half * 2]     = pack2(lo0, lo1);
            pl[kc][half * 2 + 1] = pack2(lo2, lo3);
        }
    }

#pragma unroll
    for (int kc = 0; kc < 4; ++kc) {
        const int r = kc * 16 + (lane & 7) + ((lane >> 3) & 1) * 8;
#pragma unroll
        for (int dp = 0; dp < 4; ++dp) {
            const int ch = dp * 2 + (lane >> 4);
            const uint32_t sw = (uint32_t)(ch ^ (r & 7)) << 4;
            uint32_t vh[4], vl[4];
            ldm_x4_t(vh, Vh + r * 128 + sw);
            ldm_x4_t(vl, Vl + r * 128 + sw);
            mma16816(o[dp * 2],     ph[kc], vh);
            mma16816(o[dp * 2 + 1], ph[kc], vh + 2);
            mma16816(o[dp * 2],     pl[kc], vh);
            mma16816(o[dp * 2 + 1], pl[kc], vh + 2);
            mma16816(o[dp * 2],     ph[kc], vl);
            mma16816(o[dp * 2 + 1], ph[kc], vl + 2);
        }
    }
}

__global__ __launch_bounds__(256, 1) void attn_kernel()
{
    extern __shared__ __align__(1024) char smem[];
    const uint32_t sbase = smem_u32(smem);

    const int bh = blockIdx.y;
    const int qb = (int)gridDim.x - 1 - (int)blockIdx.x;  // reversed for balance
    const int q0 = qb * 64;
    const int tid = threadIdx.x, lane = tid & 31, wid = tid >> 5;
    const int grp = wid >> 2;                  // 0 or 1
    const int gtid = tid & 127;
    const int qw = q0 + (wid & 3) * 16;        // warp's 16 q rows
    const uint32_t grp_base = sbase + grp * ATT_GRP;

    // Q' fragments (persist in regs): 4 d16-chunks, hi and lo
    uint32_t aqh[4][4], aql[4][4];
    {
        const uint32_t* q32 = reinterpret_cast<const uint32_t*>(g_qs) + (size_t)bh * TT * 64;
        const uint32_t* r0p = q32 + (size_t)(qw + (lane >> 2)) * 64;
        const uint32_t* r1p = r0p + 8 * 64;
        const int c0 = lane & 3;
#pragma unroll
        for (int k = 0; k < 4; ++k) {
            aqh[k][0] = r0p[k * 8 + c0];
            aqh[k][1] = r1p[k * 8 + c0];
            aqh[k][2] = r0p[k * 8 + 4 + c0];
            aqh[k][3] = r1p[k * 8 + 4 + c0];
            aql[k][0] = r0p[32 + k * 8 + c0];
            aql[k][1] = r1p[32 + k * 8 + c0];
            aql[k][2] = r0p[32 + k * 8 + 4 + c0];
            aql[k][3] = r1p[32 + k * 8 + 4 + c0];
        }
    }

    float o[8][4];
#pragma unroll
    for (int i = 0; i < 8; i++)
#pragma unroll
        for (int j = 0; j < 4; j++) o[i][j] = 0.f;
    float m0r = -INFINITY, m1r = -INFINITY, l0 = 0.f, l1 = 0.f;

    const char* ksrc_base = reinterpret_cast<const char*>(g_ks) + (size_t)bh * TT * 256;
    const char* vsrc_base = reinterpret_cast<const char*>(g_vs) + (size_t)bh * TT * 256;

    // Guarded prefetch: loads only when block valid, ALWAYS commits.
    auto prefetchKV = [&](int kb, int stg) {
        if (kb <= qb) {
            const uint32_t dst = grp_base + stg * ATT_STAGE;
            const char* ks = ksrc_base + (size_t)kb * 64 * 256;
            const char* vs = vsrc_base + (size_t)kb * 64 * 256;
#pragma unroll
            for (int it = 0; it < 16; ++it) {
                const int idx = gtid + it * 128;       // 0..2047
                const int mat = idx >> 10;             // 0 = K, 1 = V
                const int rem = idx & 1023;
                const int sub = rem >> 9;              // 0 = hi, 1 = lo
                const int r = (rem >> 3) & 63;
                const int ch = rem & 7;
                const char* src = (mat ? vs : ks) + (size_t)r * 256 + sub * 128 + ch * 16;
                cp16(dst + mat * 16384 + sub * 8192 + r * 128 +
                         ((uint32_t)(ch ^ (r & 7)) << 4), src);
            }
        }
        CP_COMMIT();
    };

    float sA[8][4], sB[8][4];

    // Preamble: fill 3 stages, compute S for first block.
    prefetchKV(grp,     0);     // C0
    prefetchKV(grp + 2, 1);     // C1
    prefetchKV(grp + 4, 2);     // C2
    CP_WAIT2();                 // C0 done
    BAR_SYNC(4 + grp);
    if (grp <= qb) compute_S(sA, grp_base, aqh, aql, lane);

    // Pipelined main loop (macro keeps s buffers in registers).
#define ATT_ITER(SCUR, SNEXT, KB) do {                                        \
        CP_WAIT1();                                                           \
        BAR_SYNC(4 + grp);                                                    \
        const int stc_ = (((KB) - grp) >> 1) % 3;                             \
        const uint32_t baseC_ = grp_base + (uint32_t)stc_ * ATT_STAGE;        \
        const uint32_t baseN_ = grp_base + (uint32_t)((stc_ + 1) % 3) * ATT_STAGE; \
        compute_S(SNEXT, baseN_, aqh, aql, lane);                             \
        softmax_pv(SCUR, baseC_, (KB) * 64, qw, lane, o, m0r, m1r, l0, l1);   \
        BAR_SYNC(4 + grp);                                                    \
        prefetchKV((KB) + 6, stc_);                                           \
    } while (0)

    if (grp <= qb) {
        int kb = grp;
        for (;;) {
            ATT_ITER(sA, sB, kb);
            kb += 2; if (kb > qb) break;
            ATT_ITER(sB, sA, kb);
            kb += 2; if (kb > qb) break;
        }
    }
#undef ATT_ITER

    // ---- merge the two groups' partial softmax states ----
    float* xch = reinterpret_cast<float*>(smem + ATT_GRP) + (size_t)gtid * 37;
    if (grp == 1) {
        xch[0] = m0r; xch[1] = m1r; xch[2] = l0; xch[3] = l1;
#pragma unroll
        for (int nt = 0; nt < 8; ++nt) {
            xch[4 + nt * 4 + 0] = o[nt][0];
            xch[4 + nt * 4 + 1] = o[nt][1];
            xch[4 + nt * 4 + 2] = o[nt][2];
            xch[4 + nt * 4 + 3] = o[nt][3];
        }
    }
    __syncthreads();
    if (grp == 1) return;

    {
        const float mb0 = xch[0], mb1 = xch[1];
        const float lb0 = xch[2], lb1 = xch[3];
        const float mn0 = fmaxf(m0r, mb0), mn1 = fmaxf(m1r, mb1);
        const float ca0 = __expf(m0r - mn0), cb0 = __expf(mb0 - mn0);
        const float ca1 = __expf(m1r - mn1), cb1 = __expf(mb1 - mn1);
        l0 = l0 * ca0 + lb0 * cb0;
        l1 = l1 * ca1 + lb1 * cb1;
#pragma unroll
        for (int nt = 0; nt < 8; ++nt) {
            o[nt][0] = o[nt][0] * ca0 + xch[4 + nt * 4 + 0] * cb0;
            o[nt][1] = o[nt][1] * ca0 + xch[4 + nt * 4 + 1] * cb0;
            o[nt][2] = o[nt][2] * ca1 + xch[4 + nt * 4 + 2] * cb1;
            o[nt][3] = o[nt][3] * ca1 + xch[4 + nt * 4 + 3] * cb1;
        }
    }

    // ---- epilogue: O/l, write [ah|al] proj-A layout ----
    l0 += __shfl_xor_sync(0xffffffffu, l0, 1);
    l0 += __shfl_xor_sync(0xffffffffu, l0, 2);
    l1 += __shfl_xor_sync(0xffffffffu, l1, 1);
    l1 += __shfl_xor_sync(0xffffffffu, l1, 2);
    const float inv0 = 1.f / l0, inv1 = 1.f / l1;

    const int b = bh >> 4, hh = bh & 15;
    const int trow = qw + (lane >> 2);
    const size_t mrow = (size_t)(b * TT + trow);
#pragma unroll
    for (int nt = 0; nt < 8; ++nt) {
        const int d = nt * 8 + 2 * (lane & 3);
        const float v0 = o[nt][0] * inv0, v1 = o[nt][1] * inv0;
        const float v2 = o[nt][2] * inv1, v3 = o[nt][3] * inv1;
        __nv_bfloat16 h0, lo0, h1, lo1;
        split2(v0, h0, lo0); split2(v1, h1, lo1);
        __nv_bfloat16* p0 = g_atts + mrow * K2 + hh * 64 + d;
        *(uint32_t*)p0          = pack2(h0, h1);
        *(uint32_t*)(p0 + 1024) = pack2(lo0, lo1);
        split2(v2, h0, lo0); split2(v3, h1, lo1);
        __nv_bfloat16* p1 = g_atts + (mrow + 8) * K2 + hh * 64 + d;
        *(uint32_t*)p1          = pack2(h0, h1);
        *(uint32_t*)(p1 + 1024) = pack2(lo0, lo1);
    }
}

// ---------------------------------------------------------------------------
extern "C" void kernel_launch(void* const* d_in, const int* in_sizes, int n_in,
                              void* d_out, int out_size)
{
    const float* x  = (const float*)d_in[0];
    // d_in[1] = att_mask (causal tril) — applied analytically
    const float* wq = (const float*)d_in[2];
    const float* bq = (const float*)d_in[3];
    const float* wk = (const float*)d_in[4];
    const float* bk = (const float*)d_in[5];
    const float* wv = (const float*)d_in[6];
    const float* bv = (const float*)d_in[7];
    const float* wp = (const float*)d_in[8];
    const float* bp = (const float*)d_in[9];
    float* out = (float*)d_out;

    __nv_bfloat16 *xs, *wcat, *atts;
    cudaGetSymbolAddress((void**)&xs,   g_xs);
    cudaGetSymbolAddress((void**)&wcat, g_wcat);
    cudaGetSymbolAddress((void**)&atts, g_atts);

    cudaFuncSetAttribute(hmma_gemm<0>, cudaFuncAttributeMaxDynamicSharedMemorySize, GEMM_SMEM);
    cudaFuncSetAttribute(hmma_gemm<1>, cudaFuncAttributeMaxDynamicSharedMemorySize, GEMM_SMEM);
    cudaFuncSetAttribute(attn_kernel,  cudaFuncAttributeMaxDynamicSharedMemorySize, ATT_SMEM);

    // 1) hi/lo splits
    split_x_kernel<<<MTOT, 256>>>(x, xs);
    {
        W4 w;
        w.in[0] = wq; w.in[1] = wk; w.in[2] = wv; w.in[3] = wp;
        dim3 grid(CC, 4);
        split_w4_kernel<<<grid, 256>>>(w);
    }

    // 2) QKV projections (HMMA) -> Q'/K'/V' [h|l] layouts
    {
        GemmP p;
        p.A = xs;
        p.W[0] = wcat + 0 * (size_t)WSZ2; p.bias[0] = bq;
        p.W[1] = wcat + 1 * (size_t)WSZ2; p.bias[1] = bk;
        p.W[2] = wcat + 2 * (size_t)WSZ2; p.bias[2] = bv;
        p.fout = nullptr;
        dim3 grid(CC / 128, MTOT / 128, 3);
        hmma_gemm<1><<<grid, 256, GEMM_SMEM>>>(p);
    }

    // 3) Causal flash attention (HMMA, pipelined split-KV) -> g_atts [ah|al]
    {
        dim3 grid(TT / 64, BB * HH);
        attn_kernel<<<grid, 256, ATT_SMEM>>>();
    }

    // 4) Output projection (HMMA) -> d_out
    {
        GemmP p;
        p.A = atts;
        p.W[0] = wcat + 3 * (size_t)WSZ2; p.bias[0] = bp;
        p.W[1] = p.W[0]; p.bias[1] = bp;
        p.W[2] = p.W[0]; p.bias[2] = bp;
        p.fout = out;
        dim3 grid(CC / 128, MTOT / 128, 1);
        hmma_gemm<0><<<grid, 256, GEMM_SMEM>>>(p);
    }
}

// round 14
// speedup vs baseline: 1.1114x; 1.0131x over previous
#include <cuda_runtime.h>
#include <cuda_bf16.h>
#include <math.h>
#include <stdint.h>

// Problem constants
#define BB 2
#define TT 2048
#define CC 1024
#define HH 16
#define DD 64
#define MTOT 4096
#define K2 2048                // [hi | lo] packed K dimension
#define WSZ2 (CC * K2)

// ---------------------------------------------------------------------------
// Device scratch — all operand tensors stored as unique [hi | lo] halves.
// ---------------------------------------------------------------------------
__device__ __align__(128) __nv_bfloat16 g_xs[(size_t)MTOT * K2];        // x:   [xh | xl]
__device__ __align__(128) __nv_bfloat16 g_wcat[(size_t)4 * WSZ2];       // w*:  [Wh | Wl]
__device__ __align__(128) __nv_bfloat16 g_atts[(size_t)MTOT * K2];      // att: [ah | al]
__device__ __align__(128) __nv_bfloat16 g_qs[(size_t)BB * HH * TT * 128]; // Q' = [Qh|Ql]*0.125
__device__ __align__(128) __nv_bfloat16 g_ks[(size_t)BB * HH * TT * 128]; // K' = [Kh|Kl]
__device__ __align__(128) __nv_bfloat16 g_vs[(size_t)BB * HH * TT * 128]; // V' = [Vh|Vl]

// ---------------------------------------------------------------------------
// PTX helpers (sm_80-class ISA: compiles under compute_103)
// ---------------------------------------------------------------------------
__device__ __forceinline__ uint32_t smem_u32(const void* p) {
    return (uint32_t)__cvta_generic_to_shared(p);
}

__device__ __forceinline__ void cp16(uint32_t dst, const void* src) {
    asm volatile("cp.async.cg.shared.global [%0], [%1], 16;" :: "r"(dst), "l"(src));
}
#define CP_COMMIT() asm volatile("cp.async.commit_group;" ::: "memory")
#define CP_WAIT0()  asm volatile("cp.async.wait_group 0;" ::: "memory")
#define CP_WAIT1()  asm volatile("cp.async.wait_group 1;" ::: "memory")

#define BAR_SYNC(id) asm volatile("bar.sync %0, 128;" :: "r"(id) : "memory")

__device__ __forceinline__ void ldm_x4(uint32_t* r, uint32_t addr) {
    asm volatile("ldmatrix.sync.aligned.m8n8.x4.shared.b16 {%0,%1,%2,%3}, [%4];"
                 : "=r"(r[0]), "=r"(r[1]), "=r"(r[2]), "=r"(r[3]) : "r"(addr));
}
__device__ __forceinline__ void ldm_x4_t(uint32_t* r, uint32_t addr) {
    asm volatile("ldmatrix.sync.aligned.m8n8.x4.trans.shared.b16 {%0,%1,%2,%3}, [%4];"
                 : "=r"(r[0]), "=r"(r[1]), "=r"(r[2]), "=r"(r[3]) : "r"(addr));
}

__device__ __forceinline__ void mma16816(float* c, const uint32_t* a, const uint32_t* b) {
    asm volatile(
        "mma.sync.aligned.m16n8k16.row.col.f32.bf16.bf16.f32 "
        "{%0,%1,%2,%3}, {%4,%5,%6,%7}, {%8,%9}, {%0,%1,%2,%3};"
        : "+f"(c[0]), "+f"(c[1]), "+f"(c[2]), "+f"(c[3])
        : "r"(a[0]), "r"(a[1]), "r"(a[2]), "r"(a[3]), "r"(b[0]), "r"(b[1]));
}

__device__ __forceinline__ uint32_t pack2(__nv_bfloat16 a, __nv_bfloat16 b) {
    union { __nv_bfloat162 v; uint32_t u; } t;
    t.v = __halves2bfloat162(a, b);
    return t.u;
}
__device__ __forceinline__ void split2(float v, __nv_bfloat16& h, __nv_bfloat16& l) {
    h = __float2bfloat16(v);
    l = __float2bfloat16(v - __bfloat162float(h));
}

// ---------------------------------------------------------------------------
// bf16 hi/lo split: out row = [hi(1024) | lo(1024)].
// ---------------------------------------------------------------------------
__device__ __forceinline__ void split_row(const float* __restrict__ in,
                                          __nv_bfloat16* __restrict__ out,
                                          size_t r, int k)
{
    float4 v = *reinterpret_cast<const float4*>(in + r * CC + k);
    float f[4] = {v.x, v.y, v.z, v.w};
    __nv_bfloat16 hi[4], lo[4];
#pragma unroll
    for (int i = 0; i < 4; i++) split2(f[i], hi[i], lo[i]);
    uint2 hp = make_uint2(pack2(hi[0], hi[1]), pack2(hi[2], hi[3]));
    uint2 lp = make_uint2(pack2(lo[0], lo[1]), pack2(lo[2], lo[3]));
    __nv_bfloat16* o = out + r * K2 + k;
    *reinterpret_cast<uint2*>(o)      = hp;
    *reinterpret_cast<uint2*>(o + CC) = lp;
}

__global__ __launch_bounds__(256) void split_x_kernel(const float* __restrict__ in,
                                                      __nv_bfloat16* __restrict__ out)
{
    split_row(in, out, blockIdx.x, threadIdx.x * 4);
}

struct W4 { const float* in[4]; };
__global__ __launch_bounds__(256) void split_w4_kernel(W4 p)
{
    const int w = blockIdx.y;
    split_row(p.in[w], g_wcat + (size_t)w * WSZ2, blockIdx.x, threadIdx.x * 4);
}

// ---------------------------------------------------------------------------
// HMMA GEMM (R13 version — resequenced kk body, no spills under 128 cap)
// ---------------------------------------------------------------------------
struct GemmP {
    const __nv_bfloat16* A;
    const __nv_bfloat16* W[3];
    const float* bias[3];
    float* fout;
};

#define GEMM_NCH 32
#define GEMM_STAGE 32768       // A tile 16KB + W tile 16KB
#define GEMM_SMEM (3 * GEMM_STAGE)

template <int KIND>
__global__ __launch_bounds__(256, 2) void hmma_gemm(GemmP p)
{
    const int z = blockIdx.z;
    const __nv_bfloat16* __restrict__ A = p.A;
    const __nv_bfloat16* __restrict__ W = p.W[z];
    const float* __restrict__ bias = p.bias[z];

    extern __shared__ __align__(1024) char smem[];
    const uint32_t sbase = smem_u32(smem);

    const int m0 = blockIdx.y * 128, n0 = blockIdx.x * 128;
    const int tid = threadIdx.x, lane = tid & 31, wid = tid >> 5;
    const int wm = wid >> 2, wn = wid & 3;

    const __nv_bfloat16* Arow = A + (size_t)m0 * K2;
    const __nv_bfloat16* Wrow = W + (size_t)n0 * K2;

    auto prefetch = [&](int c, int buf) {
        if (c < GEMM_NCH) {
            const uint32_t dst0 = sbase + buf * GEMM_STAGE;
#pragma unroll
            for (int it = 0; it < 8; ++it) {
                const int idx = tid + it * 256;        // 0..2047
                const int mat = idx >> 10;             // 0 = A, 1 = W
                const int rem = idx & 1023;
                const int r = rem >> 3, ch = rem & 7;
                const int col = c * 32 + (ch & 3) * 8 + (ch >> 2) * CC;
                const __nv_bfloat16* src =
                    (mat ? Wrow : Arow) + (size_t)r * K2 + col;
                cp16(dst0 + mat * 16384 + r * 128 + ((uint32_t)(ch ^ (r & 7)) << 4), src);
            }
        }
        CP_COMMIT();
    };

    float acc[4][4][4];
#pragma unroll
    for (int i = 0; i < 4; i++)
#pragma unroll
        for (int j = 0; j < 4; j++)
#pragma unroll
            for (int q = 0; q < 4; q++) acc[i][j][q] = 0.f;

    prefetch(0, 0);
    prefetch(1, 1);

    for (int kc = 0; kc < GEMM_NCH; ++kc) {
        if (kc == GEMM_NCH - 1) { CP_WAIT0(); } else { CP_WAIT1(); }
        __syncthreads();
        prefetch(kc + 2, (kc + 2) % 3);

        const uint32_t bufA = sbase + (kc % 3) * GEMM_STAGE;
        const uint32_t bufW = bufA + 16384;
#pragma unroll
        for (int kk = 0; kk < 2; ++kk) {
            uint32_t bh[4][2];
#pragma unroll
            for (int pr = 0; pr < 2; ++pr) {
                const int r = wn * 32 + pr * 16 + (lane & 7) + ((lane >> 4) << 3);
                const int ch = kk * 2 + ((lane >> 3) & 1);
                uint32_t t4[4];
                ldm_x4(t4, bufW + r * 128 + ((uint32_t)(ch ^ (r & 7)) << 4));
                bh[pr * 2][0] = t4[0]; bh[pr * 2][1] = t4[1];
                bh[pr * 2 + 1][0] = t4[2]; bh[pr * 2 + 1][1] = t4[3];
            }
            uint32_t ah[4][4];
#pragma unroll
            for (int mt = 0; mt < 4; ++mt) {
                const int r = wm * 64 + mt * 16 + (lane & 15);
                const int ch = kk * 2 + (lane >> 4);
                ldm_x4(ah[mt], bufA + r * 128 + ((uint32_t)(ch ^ (r & 7)) << 4));
            }
#pragma unroll
            for (int mt = 0; mt < 4; ++mt)
#pragma unroll
                for (int nt = 0; nt < 4; ++nt)
                    mma16816(acc[mt][nt], ah[mt], bh[nt]);
            {
                uint32_t bl[4][2];
#pragma unroll
                for (int pr = 0; pr < 2; ++pr) {
                    const int r = wn * 32 + pr * 16 + (lane & 7) + ((lane >> 4) << 3);
                    const int ch = kk * 2 + ((lane >> 3) & 1) + 4;
                    uint32_t t4[4];
                    ldm_x4(t4, bufW + r * 128 + ((uint32_t)(ch ^ (r & 7)) << 4));
                    bl[pr * 2][0] = t4[0]; bl[pr * 2][1] = t4[1];
                    bl[pr * 2 + 1][0] = t4[2]; bl[pr * 2 + 1][1] = t4[3];
                }
#pragma unroll
                for (int mt = 0; mt < 4; ++mt)
#pragma unroll
                    for (int nt = 0; nt < 4; ++nt)
                        mma16816(acc[mt][nt], ah[mt], bl[nt]);
            }
            {
                uint32_t al[4][4];
#pragma unroll
                for (int mt = 0; mt < 4; ++mt) {
                    const int r = wm * 64 + mt * 16 + (lane & 15);
                    const int ch = kk * 2 + (lane >> 4);
                    ldm_x4(al[mt], bufA + r * 128 + ((uint32_t)((ch + 4) ^ (r & 7)) << 4));
                }
#pragma unroll
                for (int mt = 0; mt < 4; ++mt)
#pragma unroll
                    for (int nt = 0; nt < 4; ++nt)
                        mma16816(acc[mt][nt], al[mt], bh[nt]);
            }
        }
    }

    // Epilogue
    const int r0g = m0 + wm * 64 + (lane >> 2);
    const int nbase = n0 + wn * 32 + 2 * (lane & 3);
#pragma unroll
    for (int mt = 0; mt < 4; ++mt) {
        const int m = r0g + mt * 16;
#pragma unroll
        for (int nt = 0; nt < 4; ++nt) {
            const int n = nbase + nt * 8;
            float v0 = acc[mt][nt][0] + bias[n];
            float v1 = acc[mt][nt][1] + bias[n + 1];
            float v2 = acc[mt][nt][2] + bias[n];
            float v3 = acc[mt][nt][3] + bias[n + 1];
            if (KIND == 0) {
                *reinterpret_cast<float2*>(p.fout + (size_t)m * CC + n) = make_float2(v0, v1);
                *reinterpret_cast<float2*>(p.fout + (size_t)(m + 8) * CC + n) = make_float2(v2, v3);
            } else {
                if (z == 0) { v0 *= 0.125f; v1 *= 0.125f; v2 *= 0.125f; v3 *= 0.125f; }
                __nv_bfloat16* target = (z == 0) ? g_qs : (z == 1) ? g_ks : g_vs;
                const int hh = n >> 6, d = n & 63;
#pragma unroll
                for (int rr = 0; rr < 2; ++rr) {
                    const int mm = m + rr * 8;
                    const float a0 = rr ? v2 : v0, a1 = rr ? v3 : v1;
                    const int b = mm >> 11, t = mm & (TT - 1);
                    const size_t row = ((size_t)(b * HH + hh)) * TT + t;
                    __nv_bfloat16 h0, l0, h1, l1;
                    split2(a0, h0, l0);
                    split2(a1, h1, l1);
                    __nv_bfloat16* q = target + row * 128 + d;
                    *(uint32_t*)q        = pack2(h0, h1);
                    *(uint32_t*)(q + 64) = pack2(l0, l1);
                }
            }
        }
    }
}

// ---------------------------------------------------------------------------
// Flash attention — split-KV warp-group ping-pong (R9 loop) with ILP-
// restructured MMA issue: K/V fragments for ALL FOUR pr/dp sub-tiles are
// loaded first, then MMAs sweep pr/dp-major across all 8 accumulators, so
// each RAW chain is touched once per 8-MMA sweep (8-way ILP vs 2-way).
// Per-accumulator operation order is unchanged -> bitwise-same numerics.
// ---------------------------------------------------------------------------
#define ATT_STAGE 32768                  // Kh|Kl|Vh|Vl tiles of 8KB (64 kv rows)
#define ATT_GRP   (2 * ATT_STAGE)        // per-group ring: 64KB
#define ATT_SMEM  (2 * ATT_GRP)          // 128KB

__device__ __forceinline__ void compute_S(
    float (&s)[8][4], uint32_t Kh,
    const uint32_t (&aqh)[4][4], const uint32_t (&aql)[4][4], int lane)
{
    const uint32_t Kl = Kh + 8192;
#pragma unroll
    for (int i = 0; i < 8; i++)
#pragma unroll
        for (int j = 0; j < 4; j++) s[i][j] = 0.f;
#pragma unroll
    for (int d16 = 0; d16 < 4; ++d16) {
        const int rr = (lane & 7) + ((lane >> 4) << 3);
        const int ch = d16 * 2 + ((lane >> 3) & 1);
        uint32_t kh4[4][4];
#pragma unroll
        for (int pr = 0; pr < 4; ++pr) {
            const int r = pr * 16 + rr;
            ldm_x4(kh4[pr], Kh + r * 128 + ((uint32_t)(ch ^ (r & 7)) << 4));
        }
        // Sweep 1: aqh * Kh  (8 independent chains)
#pragma unroll
        for (int pr = 0; pr < 4; ++pr) {
            mma16816(s[pr * 2],     aqh[d16], kh4[pr]);
            mma16816(s[pr * 2 + 1], aqh[d16], kh4[pr] + 2);
        }
        // Sweep 2: aql * Kh
#pragma unroll
        for (int pr = 0; pr < 4; ++pr) {
            mma16816(s[pr * 2],     aql[d16], kh4[pr]);
            mma16816(s[pr * 2 + 1], aql[d16], kh4[pr] + 2);
        }
        uint32_t kl4[4][4];
#pragma unroll
        for (int pr = 0; pr < 4; ++pr) {
            const int r = pr * 16 + rr;
            ldm_x4(kl4[pr], Kl + r * 128 + ((uint32_t)(ch ^ (r & 7)) << 4));
        }
        // Sweep 3: aqh * Kl
#pragma unroll
        for (int pr = 0; pr < 4; ++pr) {
            mma16816(s[pr * 2],     aqh[d16], kl4[pr]);
            mma16816(s[pr * 2 + 1], aqh[d16], kl4[pr] + 2);
        }
    }
}

__device__ __forceinline__ void softmax_pv(
    float (&s)[8][4], uint32_t Kbase, int kv0, int qw, int lane,
    float (&o)[8][4], float& m0r, float& m1r, float& l0, float& l1)
{
    const uint32_t Vh = Kbase + 16384, Vl = Kbase + 24576;
    const int r0 = qw + (lane >> 2), r1 = r0 + 8;
    if (kv0 + 63 > qw) {  // causal mask (diagonal block only)
#pragma unroll
        for (int nt = 0; nt < 8; ++nt) {
            const int j = kv0 + nt * 8 + 2 * (lane & 3);
            if (j > r0)     s[nt][0] = -INFINITY;
            if (j + 1 > r0) s[nt][1] = -INFINITY;
            if (j > r1)     s[nt][2] = -INFINITY;
            if (j + 1 > r1) s[nt][3] = -INFINITY;
        }
    }

    float b0 = -INFINITY, b1 = -INFINITY;
#pragma unroll
    for (int nt = 0; nt < 8; ++nt) {
        b0 = fmaxf(b0, fmaxf(s[nt][0], s[nt][1]));
        b1 = fmaxf(b1, fmaxf(s[nt][2], s[nt][3]));
    }
    b0 = fmaxf(b0, __shfl_xor_sync(0xffffffffu, b0, 1));
    b0 = fmaxf(b0, __shfl_xor_sync(0xffffffffu, b0, 2));
    b1 = fmaxf(b1, __shfl_xor_sync(0xffffffffu, b1, 1));
    b1 = fmaxf(b1, __shfl_xor_sync(0xffffffffu, b1, 2));
    const float mn0 = fmaxf(m0r, b0), mn1 = fmaxf(m1r, b1);
    const float cor0 = __expf(m0r - mn0), cor1 = __expf(m1r - mn1);
    m0r = mn0; m1r = mn1;
    l0 *= cor0; l1 *= cor1;
#pragma unroll
    for (int nt = 0; nt < 8; ++nt) {
        o[nt][0] *= cor0; o[nt][1] *= cor0;
        o[nt][2] *= cor1; o[nt][3] *= cor1;
    }

    uint32_t ph[4][4], pl[4][4];
#pragma unroll
    for (int kc = 0; kc < 4; ++kc) {
#pragma unroll
        for (int half = 0; half < 2; ++half) {
            const int nt = kc * 2 + half;
            const float p0 = __expf(s[nt][0] - mn0);
            const float p1 = __expf(s[nt][1] - mn0);
            const float p2 = __expf(s[nt][2] - mn1);
            const float p3 = __expf(s[nt][3] - mn1);
            l0 += p0 + p1; l1 += p2 + p3;
            __nv_bfloat16 h0, lo0, h1, lo1, h2, lo2, h3, lo3;
            split2(p0, h0, lo0); split2(p1, h1, lo1);
            split2(p2, h2, lo2); split2(p3, h3, lo3);
            ph[kc][half * 2]     = pack2(h0, h1);
            ph[kc][half * 2 + 1] = pack2(h2, h3);
            pl[kc][half * 2]     = pack2(lo0, lo1);
            pl[kc][half * 2 + 1] = pack2(lo2, lo3);
        }
    }

    // PV with dp-major MMA sweeps (8 independent o-chains per sweep).
#pragma unroll
    for (int kc = 0; kc < 4; ++kc) {
        const int r = kc * 16 + (lane & 7) + ((lane >> 3) & 1) * 8;
        uint32_t vh[4][4], vl[4][4];
#pragma unroll
        for (int dp = 0; dp < 4; ++dp) {
            const int ch = dp * 2 + (lane >> 4);
            const uint32_t sw = (uint32_t)(ch ^ (r & 7)) << 4;
            ldm_x4_t(vh[dp], Vh + r * 128 + sw);
            ldm_x4_t(vl[dp], Vl + r * 128 + sw);
        }
#pragma unroll
        for (int dp = 0; dp < 4; ++dp) {
            mma16816(o[dp * 2],     ph[kc], vh[dp]);
            mma16816(o[dp * 2 + 1], ph[kc], vh[dp] + 2);
        }
#pragma unroll
        for (int dp = 0; dp < 4; ++dp) {
            mma16816(o[dp * 2],     pl[kc], vh[dp]);
            mma16816(o[dp * 2 + 1], pl[kc], vh[dp] + 2);
        }
#pragma unroll
        for (int dp = 0; dp < 4; ++dp) {
            mma16816(o[dp * 2],     ph[kc], vl[dp]);
            mma16816(o[dp * 2 + 1], ph[kc], vl[dp] + 2);
        }
    }
}

__global__ __launch_bounds__(256, 1) void attn_kernel()
{
    extern __shared__ __align__(1024) char smem[];
    const uint32_t sbase = smem_u32(smem);

    const int bh = blockIdx.y;
    const int qb = (int)gridDim.x - 1 - (int)blockIdx.x;  // reversed for balance
    const int q0 = qb * 64;
    const int tid = threadIdx.x, lane = tid & 31, wid = tid >> 5;
    const int grp = wid >> 2;                  // 0 or 1
    const int gtid = tid & 127;
    const int qw = q0 + (wid & 3) * 16;        // warp's 16 q rows
    const uint32_t grp_base = sbase + grp * ATT_GRP;

    // Q' fragments (persist in regs): 4 d16-chunks, hi and lo
    uint32_t aqh[4][4], aql[4][4];
    {
        const uint32_t* q32 = reinterpret_cast<const uint32_t*>(g_qs) + (size_t)bh * TT * 64;
        const uint32_t* r0p = q32 + (size_t)(qw + (lane >> 2)) * 64;
        const uint32_t* r1p = r0p + 8 * 64;
        const int c0 = lane & 3;
#pragma unroll
        for (int k = 0; k < 4; ++k) {
            aqh[k][0] = r0p[k * 8 + c0];
            aqh[k][1] = r1p[k * 8 + c0];
            aqh[k][2] = r0p[k * 8 + 4 + c0];
            aqh[k][3] = r1p[k * 8 + 4 + c0];
            aql[k][0] = r0p[32 + k * 8 + c0];
            aql[k][1] = r1p[32 + k * 8 + c0];
            aql[k][2] = r0p[32 + k * 8 + 4 + c0];
            aql[k][3] = r1p[32 + k * 8 + 4 + c0];
        }
    }

    float o[8][4];
#pragma unroll
    for (int i = 0; i < 8; i++)
#pragma unroll
        for (int j = 0; j < 4; j++) o[i][j] = 0.f;
    float m0r = -INFINITY, m1r = -INFINITY, l0 = 0.f, l1 = 0.f;

    const char* ksrc_base = reinterpret_cast<const char*>(g_ks) + (size_t)bh * TT * 256;
    const char* vsrc_base = reinterpret_cast<const char*>(g_vs) + (size_t)bh * TT * 256;

    auto prefetchKV = [&](int kb, int stg) {
        if (kb <= qb) {
            const uint32_t dst = grp_base + stg * ATT_STAGE;
            const char* ks = ksrc_base + (size_t)kb * 64 * 256;
            const char* vs = vsrc_base + (size_t)kb * 64 * 256;
#pragma unroll
            for (int it = 0; it < 16; ++it) {
                const int idx = gtid + it * 128;       // 0..2047
                const int mat = idx >> 10;             // 0 = K, 1 = V
                const int rem = idx & 1023;
                const int sub = rem >> 9;              // 0 = hi, 1 = lo
                const int r = (rem >> 3) & 63;
                const int ch = rem & 7;
                const char* src = (mat ? vs : ks) + (size_t)r * 256 + sub * 128 + ch * 16;
                cp16(dst + mat * 16384 + sub * 8192 + r * 128 +
                         ((uint32_t)(ch ^ (r & 7)) << 4), src);
            }
        }
        CP_COMMIT();
    };

    // Group g handles blocks {g, g+2, ...} within [0, qb].
    int stg = 0;
    if (grp <= qb) prefetchKV(grp, 0);

    for (int kb = grp; kb <= qb; kb += 2) {
        CP_WAIT0();
        BAR_SYNC(4 + grp);                       // group-local barrier
        prefetchKV(kb + 2, stg ^ 1);

        const uint32_t Kbase = grp_base + stg * ATT_STAGE;
        stg ^= 1;

        float s[8][4];
        compute_S(s, Kbase, aqh, aql, lane);
        softmax_pv(s, Kbase, kb * 64, qw, lane, o, m0r, m1r, l0, l1);
    }

    // ---- merge the two groups' partial softmax states ----
    float* xch = reinterpret_cast<float*>(smem + ATT_GRP) + (size_t)gtid * 37;
    if (grp == 1) {
        xch[0] = m0r; xch[1] = m1r; xch[2] = l0; xch[3] = l1;
#pragma unroll
        for (int nt = 0; nt < 8; ++nt) {
            xch[4 + nt * 4 + 0] = o[nt][0];
            xch[4 + nt * 4 + 1] = o[nt][1];
            xch[4 + nt * 4 + 2] = o[nt][2];
            xch[4 + nt * 4 + 3] = o[nt][3];
        }
    }
    __syncthreads();
    if (grp == 1) return;

    {
        const float mb0 = xch[0], mb1 = xch[1];
        const float lb0 = xch[2], lb1 = xch[3];
        const float mn0 = fmaxf(m0r, mb0), mn1 = fmaxf(m1r, mb1);
        const float ca0 = __expf(m0r - mn0), cb0 = __expf(mb0 - mn0);
        const float ca1 = __expf(m1r - mn1), cb1 = __expf(mb1 - mn1);
        l0 = l0 * ca0 + lb0 * cb0;
        l1 = l1 * ca1 + lb1 * cb1;
#pragma unroll
        for (int nt = 0; nt < 8; ++nt) {
            o[nt][0] = o[nt][0] * ca0 + xch[4 + nt * 4 + 0] * cb0;
            o[nt][1] = o[nt][1] * ca0 + xch[4 + nt * 4 + 1] * cb0;
            o[nt][2] = o[nt][2] * ca1 + xch[4 + nt * 4 + 2] * cb1;
            o[nt][3] = o[nt][3] * ca1 + xch[4 + nt * 4 + 3] * cb1;
        }
    }

    // ---- epilogue: O/l, write [ah|al] proj-A layout ----
    l0 += __shfl_xor_sync(0xffffffffu, l0, 1);
    l0 += __shfl_xor_sync(0xffffffffu, l0, 2);
    l1 += __shfl_xor_sync(0xffffffffu, l1, 1);
    l1 += __shfl_xor_sync(0xffffffffu, l1, 2);
    const float inv0 = 1.f / l0, inv1 = 1.f / l1;

    const int b = bh >> 4, hh = bh & 15;
    const int trow = qw + (lane >> 2);
    const size_t mrow = (size_t)(b * TT + trow);
#pragma unroll
    for (int nt = 0; nt < 8; ++nt) {
        const int d = nt * 8 + 2 * (lane & 3);
        const float v0 = o[nt][0] * inv0, v1 = o[nt][1] * inv0;
        const float v2 = o[nt][2] * inv1, v3 = o[nt][3] * inv1;
        __nv_bfloat16 h0, lo0, h1, lo1;
        split2(v0, h0, lo0); split2(v1, h1, lo1);
        __nv_bfloat16* p0 = g_atts + mrow * K2 + hh * 64 + d;
        *(uint32_t*)p0          = pack2(h0, h1);
        *(uint32_t*)(p0 + 1024) = pack2(lo0, lo1);
        split2(v2, h0, lo0); split2(v3, h1, lo1);
        __nv_bfloat16* p1 = g_atts + (mrow + 8) * K2 + hh * 64 + d;
        *(uint32_t*)p1          = pack2(h0, h1);
        *(uint32_t*)(p1 + 1024) = pack2(lo0, lo1);
    }
}

// ---------------------------------------------------------------------------
extern "C" void kernel_launch(void* const* d_in, const int* in_sizes, int n_in,
                              void* d_out, int out_size)
{
    const float* x  = (const float*)d_in[0];
    // d_in[1] = att_mask (causal tril) — applied analytically
    const float* wq = (const float*)d_in[2];
    const float* bq = (const float*)d_in[3];
    const float* wk = (const float*)d_in[4];
    const float* bk = (const float*)d_in[5];
    const float* wv = (const float*)d_in[6];
    const float* bv = (const float*)d_in[7];
    const float* wp = (const float*)d_in[8];
    const float* bp = (const float*)d_in[9];
    float* out = (float*)d_out;

    __nv_bfloat16 *xs, *wcat, *atts;
    cudaGetSymbolAddress((void**)&xs,   g_xs);
    cudaGetSymbolAddress((void**)&wcat, g_wcat);
    cudaGetSymbolAddress((void**)&atts, g_atts);

    cudaFuncSetAttribute(hmma_gemm<0>, cudaFuncAttributeMaxDynamicSharedMemorySize, GEMM_SMEM);
    cudaFuncSetAttribute(hmma_gemm<1>, cudaFuncAttributeMaxDynamicSharedMemorySize, GEMM_SMEM);
    cudaFuncSetAttribute(attn_kernel,  cudaFuncAttributeMaxDynamicSharedMemorySize, ATT_SMEM);

    // 1) hi/lo splits
    split_x_kernel<<<MTOT, 256>>>(x, xs);
    {
        W4 w;
        w.in[0] = wq; w.in[1] = wk; w.in[2] = wv; w.in[3] = wp;
        dim3 grid(CC, 4);
        split_w4_kernel<<<grid, 256>>>(w);
    }

    // 2) QKV projections (HMMA) -> Q'/K'/V' [h|l] layouts
    {
        GemmP p;
        p.A = xs;
        p.W[0] = wcat + 0 * (size_t)WSZ2; p.bias[0] = bq;
        p.W[1] = wcat + 1 * (size_t)WSZ2; p.bias[1] = bk;
        p.W[2] = wcat + 2 * (size_t)WSZ2; p.bias[2] = bv;
        p.fout = nullptr;
        dim3 grid(CC / 128, MTOT / 128, 3);
        hmma_gemm<1><<<grid, 256, GEMM_SMEM>>>(p);
    }

    // 3) Causal flash attention (HMMA, split-KV warp groups) -> g_atts [ah|al]
    {
        dim3 grid(TT / 64, BB * HH);
        attn_kernel<<<grid, 256, ATT_SMEM>>>();
    }

    // 4) Output projection (HMMA) -> d_out
    {
        GemmP p;
        p.A = atts;
        p.W[0] = wcat + 3 * (size_t)WSZ2; p.bias[0] = bp;
        p.W[1] = p.W[0]; p.bias[1] = bp;
        p.W[2] = p.W[0]; p.bias[2] = bp;
        p.fout = out;
        dim3 grid(CC / 128, MTOT / 128, 1);
        hmma_gemm<0><<<grid, 256, GEMM_SMEM>>>(p);
    }
}

// round 15
// speedup vs baseline: 1.4331x; 1.2895x over previous
#include <cuda_runtime.h>
#include <cuda_bf16.h>
#include <cuda_fp16.h>
#include <math.h>
#include <stdint.h>

// Problem constants
#define BB 2
#define TT 2048
#define CC 1024
#define HH 16
#define DD 64
#define MTOT 4096
#define K2 2048                // [hi | lo] packed K dimension
#define WSZ2 (CC * K2)

// ---------------------------------------------------------------------------
// Device scratch. GEMM operands are fp16 [hi|lo] (activations) / fp16 hi
// (weights; lo stored but unused). Attention operands stay bf16 [hi|lo].
// ---------------------------------------------------------------------------
__device__ __align__(128) __half g_xs[(size_t)MTOT * K2];               // x:   [xh | xl] fp16
__device__ __align__(128) __half g_wcat[(size_t)4 * WSZ2];              // w*:  [Wh | Wl] fp16
__device__ __align__(128) __half g_atts[(size_t)MTOT * K2];             // att: [ah | al] fp16
__device__ __align__(128) __nv_bfloat16 g_qs[(size_t)BB * HH * TT * 128]; // Q' = [Qh|Ql]*0.125 bf16
__device__ __align__(128) __nv_bfloat16 g_ks[(size_t)BB * HH * TT * 128]; // K' = [Kh|Kl] bf16
__device__ __align__(128) __nv_bfloat16 g_vs[(size_t)BB * HH * TT * 128]; // V' = [Vh|Vl] bf16

// ---------------------------------------------------------------------------
// PTX helpers (sm_80-class ISA: compiles under compute_103)
// ---------------------------------------------------------------------------
__device__ __forceinline__ uint32_t smem_u32(const void* p) {
    return (uint32_t)__cvta_generic_to_shared(p);
}

__device__ __forceinline__ void cp16(uint32_t dst, const void* src) {
    asm volatile("cp.async.cg.shared.global [%0], [%1], 16;" :: "r"(dst), "l"(src));
}
#define CP_COMMIT() asm volatile("cp.async.commit_group;" ::: "memory")
#define CP_WAIT0()  asm volatile("cp.async.wait_group 0;" ::: "memory")
#define CP_WAIT1()  asm volatile("cp.async.wait_group 1;" ::: "memory")

#define BAR_SYNC(id) asm volatile("bar.sync %0, 128;" :: "r"(id) : "memory")

__device__ __forceinline__ void ldm_x4(uint32_t* r, uint32_t addr) {
    asm volatile("ldmatrix.sync.aligned.m8n8.x4.shared.b16 {%0,%1,%2,%3}, [%4];"
                 : "=r"(r[0]), "=r"(r[1]), "=r"(r[2]), "=r"(r[3]) : "r"(addr));
}
__device__ __forceinline__ void ldm_x4_t(uint32_t* r, uint32_t addr) {
    asm volatile("ldmatrix.sync.aligned.m8n8.x4.trans.shared.b16 {%0,%1,%2,%3}, [%4];"
                 : "=r"(r[0]), "=r"(r[1]), "=r"(r[2]), "=r"(r[3]) : "r"(addr));
}

// bf16 MMA (attention)
__device__ __forceinline__ void mma16816(float* c, const uint32_t* a, const uint32_t* b) {
    asm volatile(
        "mma.sync.aligned.m16n8k16.row.col.f32.bf16.bf16.f32 "
        "{%0,%1,%2,%3}, {%4,%5,%6,%7}, {%8,%9}, {%0,%1,%2,%3};"
        : "+f"(c[0]), "+f"(c[1]), "+f"(c[2]), "+f"(c[3])
        : "r"(a[0]), "r"(a[1]), "r"(a[2]), "r"(a[3]), "r"(b[0]), "r"(b[1]));
}
// fp16 MMA (projections)
__device__ __forceinline__ void mma16816h(float* c, const uint32_t* a, const uint32_t* b) {
    asm volatile(
        "mma.sync.aligned.m16n8k16.row.col.f32.f16.f16.f32 "
        "{%0,%1,%2,%3}, {%4,%5,%6,%7}, {%8,%9}, {%0,%1,%2,%3};"
        : "+f"(c[0]), "+f"(c[1]), "+f"(c[2]), "+f"(c[3])
        : "r"(a[0]), "r"(a[1]), "r"(a[2]), "r"(a[3]), "r"(b[0]), "r"(b[1]));
}

__device__ __forceinline__ uint32_t pack2(__nv_bfloat16 a, __nv_bfloat16 b) {
    union { __nv_bfloat162 v; uint32_t u; } t;
    t.v = __halves2bfloat162(a, b);
    return t.u;
}
__device__ __forceinline__ void split2(float v, __nv_bfloat16& h, __nv_bfloat16& l) {
    h = __float2bfloat16(v);
    l = __float2bfloat16(v - __bfloat162float(h));
}
__device__ __forceinline__ uint32_t pack2h(__half a, __half b) {
    union { __half2 v; uint32_t u; } t;
    t.v = __halves2half2(a, b);
    return t.u;
}
__device__ __forceinline__ void split2h(float v, __half& h, __half& l) {
    h = __float2half(v);
    l = __float2half(v - __half2float(h));
}

// ---------------------------------------------------------------------------
// fp16 hi/lo split: out row = [hi(1024) | lo(1024)].
// GEMM uses (xh+xl)*wh: activation exact to 2^-22, weight rounded to 2^-12.
// ---------------------------------------------------------------------------
__device__ __forceinline__ void split_row_h(const float* __restrict__ in,
                                            __half* __restrict__ out,
                                            size_t r, int k)
{
    float4 v = *reinterpret_cast<const float4*>(in + r * CC + k);
    float f[4] = {v.x, v.y, v.z, v.w};
    __half hi[4], lo[4];
#pragma unroll
    for (int i = 0; i < 4; i++) split2h(f[i], hi[i], lo[i]);
    uint2 hp = make_uint2(pack2h(hi[0], hi[1]), pack2h(hi[2], hi[3]));
    uint2 lp = make_uint2(pack2h(lo[0], lo[1]), pack2h(lo[2], lo[3]));
    __half* o = out + r * K2 + k;
    *reinterpret_cast<uint2*>(o)      = hp;
    *reinterpret_cast<uint2*>(o + CC) = lp;
}

__global__ __launch_bounds__(256) void split_x_kernel(const float* __restrict__ in,
                                                      __half* __restrict__ out)
{
    split_row_h(in, out, blockIdx.x, threadIdx.x * 4);
}

struct W4 { const float* in[4]; };
__global__ __launch_bounds__(256) void split_w4_kernel(W4 p)
{
    const int w = blockIdx.y;
    split_row_h(p.in[w], g_wcat + (size_t)w * WSZ2, blockIdx.x, threadIdx.x * 4);
}

// ---------------------------------------------------------------------------
// fp16 2-term HMMA GEMM: out[m,n] = sum_k A[m,k]*W[n,k] + bias[n]
// A: [M x 2048] fp16 [h|l]; W: read hi half only. acc = (ah + al) * wh.
// CTA 128x128, 8 warps (2x4), warp tile 64x32. K chunk = 64 unique k.
// Stage 48KB = Ah(16K) | Al(16K) | Wh(16K); 2-stage ring; 2 CTAs/SM.
// ---------------------------------------------------------------------------
struct GemmP {
    const __half* A;
    const __half* W[3];
    const float* bias[3];
    float* fout;
};

#define GEMM_NCH 16
#define GEMM_STAGE 49152       // Ah 16KB + Al 16KB + Wh 16KB
#define GEMM_SMEM (2 * GEMM_STAGE)

template <int KIND>
__global__ __launch_bounds__(256, 2) void hmma_gemm(GemmP p)
{
    const int z = blockIdx.z;
    const __half* __restrict__ A = p.A;
    const __half* __restrict__ W = p.W[z];
    const float* __restrict__ bias = p.bias[z];

    extern __shared__ __align__(1024) char smem[];
    const uint32_t sbase = smem_u32(smem);

    const int m0 = blockIdx.y * 128, n0 = blockIdx.x * 128;
    const int tid = threadIdx.x, lane = tid & 31, wid = tid >> 5;
    const int wm = wid >> 2, wn = wid & 3;

    const __half* Arow = A + (size_t)m0 * K2;
    const __half* Wrow = W + (size_t)n0 * K2;

    auto prefetch = [&](int c, int buf) {
        if (c < GEMM_NCH) {
            const uint32_t dst0 = sbase + buf * GEMM_STAGE;
#pragma unroll
            for (int it = 0; it < 12; ++it) {
                const int idx = tid + it * 256;        // 0..3071
                const int sub = idx >> 10;             // 0 = Ah, 1 = Al, 2 = Wh
                const int rem = idx & 1023;
                const int r = rem >> 3, ch = rem & 7;
                const int col = c * 64 + ch * 8 + ((sub == 1) ? CC : 0);
                const __half* src = ((sub == 2) ? Wrow : Arow) + (size_t)r * K2 + col;
                cp16(dst0 + sub * 16384 + r * 128 + ((uint32_t)(ch ^ (r & 7)) << 4), src);
            }
        }
        CP_COMMIT();
    };

    float acc[4][4][4];
#pragma unroll
    for (int i = 0; i < 4; i++)
#pragma unroll
        for (int j = 0; j < 4; j++)
#pragma unroll
            for (int q = 0; q < 4; q++) acc[i][j][q] = 0.f;

    prefetch(0, 0);

    for (int kc = 0; kc < GEMM_NCH; ++kc) {
        CP_WAIT0();
        __syncthreads();
        prefetch(kc + 1, (kc + 1) & 1);

        const uint32_t bufAh = sbase + (kc & 1) * GEMM_STAGE;
        const uint32_t bufAl = bufAh + 16384;
        const uint32_t bufW  = bufAh + 32768;
#pragma unroll
        for (int k16 = 0; k16 < 4; ++k16) {
            // W hi fragments
            uint32_t bh[4][2];
#pragma unroll
            for (int pr = 0; pr < 2; ++pr) {
                const int r = wn * 32 + pr * 16 + (lane & 7) + ((lane >> 4) << 3);
                const int ch = k16 * 2 + ((lane >> 3) & 1);
                uint32_t t4[4];
                ldm_x4(t4, bufW + r * 128 + ((uint32_t)(ch ^ (r & 7)) << 4));
                bh[pr * 2][0] = t4[0]; bh[pr * 2][1] = t4[1];
                bh[pr * 2 + 1][0] = t4[2]; bh[pr * 2 + 1][1] = t4[3];
            }
            // A hi fragments; ah*bh
            uint32_t ah[4][4];
#pragma unroll
            for (int mt = 0; mt < 4; ++mt) {
                const int r = wm * 64 + mt * 16 + (lane & 15);
                const int ch = k16 * 2 + (lane >> 4);
                ldm_x4(ah[mt], bufAh + r * 128 + ((uint32_t)(ch ^ (r & 7)) << 4));
            }
#pragma unroll
            for (int mt = 0; mt < 4; ++mt)
#pragma unroll
                for (int nt = 0; nt < 4; ++nt)
                    mma16816h(acc[mt][nt], ah[mt], bh[nt]);
            // A lo fragments; al*bh
            {
                uint32_t al[4][4];
#pragma unroll
                for (int mt = 0; mt < 4; ++mt) {
                    const int r = wm * 64 + mt * 16 + (lane & 15);
                    const int ch = k16 * 2 + (lane >> 4);
                    ldm_x4(al[mt], bufAl + r * 128 + ((uint32_t)(ch ^ (r & 7)) << 4));
                }
#pragma unroll
                for (int mt = 0; mt < 4; ++mt)
#pragma unroll
                    for (int nt = 0; nt < 4; ++nt)
                        mma16816h(acc[mt][nt], al[mt], bh[nt]);
            }
        }
    }

    // Epilogue
    const int r0g = m0 + wm * 64 + (lane >> 2);
    const int nbase = n0 + wn * 32 + 2 * (lane & 3);
#pragma unroll
    for (int mt = 0; mt < 4; ++mt) {
        const int m = r0g + mt * 16;
#pragma unroll
        for (int nt = 0; nt < 4; ++nt) {
            const int n = nbase + nt * 8;
            float v0 = acc[mt][nt][0] + bias[n];
            float v1 = acc[mt][nt][1] + bias[n + 1];
            float v2 = acc[mt][nt][2] + bias[n];
            float v3 = acc[mt][nt][3] + bias[n + 1];
            if (KIND == 0) {
                *reinterpret_cast<float2*>(p.fout + (size_t)m * CC + n) = make_float2(v0, v1);
                *reinterpret_cast<float2*>(p.fout + (size_t)(m + 8) * CC + n) = make_float2(v2, v3);
            } else {
                if (z == 0) { v0 *= 0.125f; v1 *= 0.125f; v2 *= 0.125f; v3 *= 0.125f; }
                __nv_bfloat16* target = (z == 0) ? g_qs : (z == 1) ? g_ks : g_vs;
                const int hh = n >> 6, d = n & 63;
#pragma unroll
                for (int rr = 0; rr < 2; ++rr) {
                    const int mm = m + rr * 8;
                    const float a0 = rr ? v2 : v0, a1 = rr ? v3 : v1;
                    const int b = mm >> 11, t = mm & (TT - 1);
                    const size_t row = ((size_t)(b * HH + hh)) * TT + t;
                    __nv_bfloat16 h0, l0, h1, l1;
                    split2(a0, h0, l0);
                    split2(a1, h1, l1);
                    __nv_bfloat16* q = target + row * 128 + d;
                    *(uint32_t*)q        = pack2(h0, h1);
                    *(uint32_t*)(q + 64) = pack2(l0, l1);
                }
            }
        }
    }
}

// ---------------------------------------------------------------------------
// Flash attention — split-KV warp-group ping-pong (R14 version, bf16 3-term,
// unchanged numerics). Epilogue writes fp16 [ah|al] for the fp16 proj GEMM.
// ---------------------------------------------------------------------------
#define ATT_STAGE 32768                  // Kh|Kl|Vh|Vl tiles of 8KB (64 kv rows)
#define ATT_GRP   (2 * ATT_STAGE)        // per-group ring: 64KB
#define ATT_SMEM  (2 * ATT_GRP)          // 128KB

__device__ __forceinline__ void compute_S(
    float (&s)[8][4], uint32_t Kh,
    const uint32_t (&aqh)[4][4], const uint32_t (&aql)[4][4], int lane)
{
    const uint32_t Kl = Kh + 8192;
#pragma unroll
    for (int i = 0; i < 8; i++)
#pragma unroll
        for (int j = 0; j < 4; j++) s[i][j] = 0.f;
#pragma unroll
    for (int d16 = 0; d16 < 4; ++d16) {
        const int rr = (lane & 7) + ((lane >> 4) << 3);
        const int ch = d16 * 2 + ((lane >> 3) & 1);
        uint32_t kh4[4][4];
#pragma unroll
        for (int pr = 0; pr < 4; ++pr) {
            const int r = pr * 16 + rr;
            ldm_x4(kh4[pr], Kh + r * 128 + ((uint32_t)(ch ^ (r & 7)) << 4));
        }
#pragma unroll
        for (int pr = 0; pr < 4; ++pr) {
            mma16816(s[pr * 2],     aqh[d16], kh4[pr]);
            mma16816(s[pr * 2 + 1], aqh[d16], kh4[pr] + 2);
        }
#pragma unroll
        for (int pr = 0; pr < 4; ++pr) {
            mma16816(s[pr * 2],     aql[d16], kh4[pr]);
            mma16816(s[pr * 2 + 1], aql[d16], kh4[pr] + 2);
        }
        uint32_t kl4[4][4];
#pragma unroll
        for (int pr = 0; pr < 4; ++pr) {
            const int r = pr * 16 + rr;
            ldm_x4(kl4[pr], Kl + r * 128 + ((uint32_t)(ch ^ (r & 7)) << 4));
        }
#pragma unroll
        for (int pr = 0; pr < 4; ++pr) {
            mma16816(s[pr * 2],     aqh[d16], kl4[pr]);
            mma16816(s[pr * 2 + 1], aqh[d16], kl4[pr] + 2);
        }
    }
}

__device__ __forceinline__ void softmax_pv(
    float (&s)[8][4], uint32_t Kbase, int kv0, int qw, int lane,
    float (&o)[8][4], float& m0r, float& m1r, float& l0, float& l1)
{
    const uint32_t Vh = Kbase + 16384, Vl = Kbase + 24576;
    const int r0 = qw + (lane >> 2), r1 = r0 + 8;
    if (kv0 + 63 > qw) {  // causal mask (diagonal block only)
#pragma unroll
        for (int nt = 0; nt < 8; ++nt) {
            const int j = kv0 + nt * 8 + 2 * (lane & 3);
            if (j > r0)     s[nt][0] = -INFINITY;
            if (j + 1 > r0) s[nt][1] = -INFINITY;
            if (j > r1)     s[nt][2] = -INFINITY;
            if (j + 1 > r1) s[nt][3] = -INFINITY;
        }
    }

    float b0 = -INFINITY, b1 = -INFINITY;
#pragma unroll
    for (int nt = 0; nt < 8; ++nt) {
        b0 = fmaxf(b0, fmaxf(s[nt][0], s[nt][1]));
        b1 = fmaxf(b1, fmaxf(s[nt][2], s[nt][3]));
    }
    b0 = fmaxf(b0, __shfl_xor_sync(0xffffffffu, b0, 1));
    b0 = fmaxf(b0, __shfl_xor_sync(0xffffffffu, b0, 2));
    b1 = fmaxf(b1, __shfl_xor_sync(0xffffffffu, b1, 1));
    b1 = fmaxf(b1, __shfl_xor_sync(0xffffffffu, b1, 2));
    const float mn0 = fmaxf(m0r, b0), mn1 = fmaxf(m1r, b1);
    const float cor0 = __expf(m0r - mn0), cor1 = __expf(m1r - mn1);
    m0r = mn0; m1r = mn1;
    l0 *= cor0; l1 *= cor1;
#pragma unroll
    for (int nt = 0; nt < 8; ++nt) {
        o[nt][0] *= cor0; o[nt][1] *= cor0;
        o[nt][2] *= cor1; o[nt][3] *= cor1;
    }

    uint32_t ph[4][4], pl[4][4];
#pragma unroll
    for (int kc = 0; kc < 4; ++kc) {
#pragma unroll
        for (int half = 0; half < 2; ++half) {
            const int nt = kc * 2 + half;
            const float p0 = __expf(s[nt][0] - mn0);
            const float p1 = __expf(s[nt][1] - mn0);
            const float p2 = __expf(s[nt][2] - mn1);
            const float p3 = __expf(s[nt][3] - mn1);
            l0 += p0 + p1; l1 += p2 + p3;
            __nv_bfloat16 h0, lo0, h1, lo1, h2, lo2, h3, lo3;
            split2(p0, h0, lo0); split2(p1, h1, lo1);
            split2(p2, h2, lo2); split2(p3, h3, lo3);
            ph[kc][half * 2]     = pack2(h0, h1);
            ph[kc][half * 2 + 1] = pack2(h2, h3);
            pl[kc][half * 2]     = pack2(lo0, lo1);
            pl[kc][half * 2 + 1] = pack2(lo2, lo3);
        }
    }

#pragma unroll
    for (int kc = 0; kc < 4; ++kc) {
        const int r = kc * 16 + (lane & 7) + ((lane >> 3) & 1) * 8;
        uint32_t vh[4][4], vl[4][4];
#pragma unroll
        for (int dp = 0; dp < 4; ++dp) {
            const int ch = dp * 2 + (lane >> 4);
            const uint32_t sw = (uint32_t)(ch ^ (r & 7)) << 4;
            ldm_x4_t(vh[dp], Vh + r * 128 + sw);
            ldm_x4_t(vl[dp], Vl + r * 128 + sw);
        }
#pragma unroll
        for (int dp = 0; dp < 4; ++dp) {
            mma16816(o[dp * 2],     ph[kc], vh[dp]);
            mma16816(o[dp * 2 + 1], ph[kc], vh[dp] + 2);
        }
#pragma unroll
        for (int dp = 0; dp < 4; ++dp) {
            mma16816(o[dp * 2],     pl[kc], vh[dp]);
            mma16816(o[dp * 2 + 1], pl[kc], vh[dp] + 2);
        }
#pragma unroll
        for (int dp = 0; dp < 4; ++dp) {
            mma16816(o[dp * 2],     ph[kc], vl[dp]);
            mma16816(o[dp * 2 + 1], ph[kc], vl[dp] + 2);
        }
    }
}

__global__ __launch_bounds__(256, 1) void attn_kernel()
{
    extern __shared__ __align__(1024) char smem[];
    const uint32_t sbase = smem_u32(smem);

    const int bh = blockIdx.y;
    const int qb = (int)gridDim.x - 1 - (int)blockIdx.x;  // reversed for balance
    const int q0 = qb * 64;
    const int tid = threadIdx.x, lane = tid & 31, wid = tid >> 5;
    const int grp = wid >> 2;                  // 0 or 1
    const int gtid = tid & 127;
    const int qw = q0 + (wid & 3) * 16;        // warp's 16 q rows
    const uint32_t grp_base = sbase + grp * ATT_GRP;

    // Q' fragments (persist in regs): 4 d16-chunks, hi and lo
    uint32_t aqh[4][4], aql[4][4];
    {
        const uint32_t* q32 = reinterpret_cast<const uint32_t*>(g_qs) + (size_t)bh * TT * 64;
        const uint32_t* r0p = q32 + (size_t)(qw + (lane >> 2)) * 64;
        const uint32_t* r1p = r0p + 8 * 64;
        const int c0 = lane & 3;
#pragma unroll
        for (int k = 0; k < 4; ++k) {
            aqh[k][0] = r0p[k * 8 + c0];
            aqh[k][1] = r1p[k * 8 + c0];
            aqh[k][2] = r0p[k * 8 + 4 + c0];
            aqh[k][3] = r1p[k * 8 + 4 + c0];
            aql[k][0] = r0p[32 + k * 8 + c0];
            aql[k][1] = r1p[32 + k * 8 + c0];
            aql[k][2] = r0p[32 + k * 8 + 4 + c0];
            aql[k][3] = r1p[32 + k * 8 + 4 + c0];
        }
    }

    float o[8][4];
#pragma unroll
    for (int i = 0; i < 8; i++)
#pragma unroll
        for (int j = 0; j < 4; j++) o[i][j] = 0.f;
    float m0r = -INFINITY, m1r = -INFINITY, l0 = 0.f, l1 = 0.f;

    const char* ksrc_base = reinterpret_cast<const char*>(g_ks) + (size_t)bh * TT * 256;
    const char* vsrc_base = reinterpret_cast<const char*>(g_vs) + (size_t)bh * TT * 256;

    auto prefetchKV = [&](int kb, int stg) {
        if (kb <= qb) {
            const uint32_t dst = grp_base + stg * ATT_STAGE;
            const char* ks = ksrc_base + (size_t)kb * 64 * 256;
            const char* vs = vsrc_base + (size_t)kb * 64 * 256;
#pragma unroll
            for (int it = 0; it < 16; ++it) {
                const int idx = gtid + it * 128;       // 0..2047
                const int mat = idx >> 10;             // 0 = K, 1 = V
                const int rem = idx & 1023;
                const int sub = rem >> 9;              // 0 = hi, 1 = lo
                const int r = (rem >> 3) & 63;
                const int ch = rem & 7;
                const char* src = (mat ? vs : ks) + (size_t)r * 256 + sub * 128 + ch * 16;
                cp16(dst + mat * 16384 + sub * 8192 + r * 128 +
                         ((uint32_t)(ch ^ (r & 7)) << 4), src);
            }
        }
        CP_COMMIT();
    };

    int stg = 0;
    if (grp <= qb) prefetchKV(grp, 0);

    for (int kb = grp; kb <= qb; kb += 2) {
        CP_WAIT0();
        BAR_SYNC(4 + grp);                       // group-local barrier
        prefetchKV(kb + 2, stg ^ 1);

        const uint32_t Kbase = grp_base + stg * ATT_STAGE;
        stg ^= 1;

        float s[8][4];
        compute_S(s, Kbase, aqh, aql, lane);
        softmax_pv(s, Kbase, kb * 64, qw, lane, o, m0r, m1r, l0, l1);
    }

    // ---- merge the two groups' partial softmax states ----
    float* xch = reinterpret_cast<float*>(smem + ATT_GRP) + (size_t)gtid * 37;
    if (grp == 1) {
        xch[0] = m0r; xch[1] = m1r; xch[2] = l0; xch[3] = l1;
#pragma unroll
        for (int nt = 0; nt < 8; ++nt) {
            xch[4 + nt * 4 + 0] = o[nt][0];
            xch[4 + nt * 4 + 1] = o[nt][1];
            xch[4 + nt * 4 + 2] = o[nt][2];
            xch[4 + nt * 4 + 3] = o[nt][3];
        }
    }
    __syncthreads();
    if (grp == 1) return;

    {
        const float mb0 = xch[0], mb1 = xch[1];
        const float lb0 = xch[2], lb1 = xch[3];
        const float mn0 = fmaxf(m0r, mb0), mn1 = fmaxf(m1r, mb1);
        const float ca0 = __expf(m0r - mn0), cb0 = __expf(mb0 - mn0);
        const float ca1 = __expf(m1r - mn1), cb1 = __expf(mb1 - mn1);
        l0 = l0 * ca0 + lb0 * cb0;
        l1 = l1 * ca1 + lb1 * cb1;
#pragma unroll
        for (int nt = 0; nt < 8; ++nt) {
            o[nt][0] = o[nt][0] * ca0 + xch[4 + nt * 4 + 0] * cb0;
            o[nt][1] = o[nt][1] * ca0 + xch[4 + nt * 4 + 1] * cb0;
            o[nt][2] = o[nt][2] * ca1 + xch[4 + nt * 4 + 2] * cb1;
            o[nt][3] = o[nt][3] * ca1 + xch[4 + nt * 4 + 3] * cb1;
        }
    }

    // ---- epilogue: O/l, write fp16 [ah|al] proj-A layout ----
    l0 += __shfl_xor_sync(0xffffffffu, l0, 1);
    l0 += __shfl_xor_sync(0xffffffffu, l0, 2);
    l1 += __shfl_xor_sync(0xffffffffu, l1, 1);
    l1 += __shfl_xor_sync(0xffffffffu, l1, 2);
    const float inv0 = 1.f / l0, inv1 = 1.f / l1;

    const int b = bh >> 4, hh = bh & 15;
    const int trow = qw + (lane >> 2);
    const size_t mrow = (size_t)(b * TT + trow);
#pragma unroll
    for (int nt = 0; nt < 8; ++nt) {
        const int d = nt * 8 + 2 * (lane & 3);
        const float v0 = o[nt][0] * inv0, v1 = o[nt][1] * inv0;
        const float v2 = o[nt][2] * inv1, v3 = o[nt][3] * inv1;
        __half h0, lo0, h1, lo1;
        split2h(v0, h0, lo0); split2h(v1, h1, lo1);
        __half* p0 = g_atts + mrow * K2 + hh * 64 + d;
        *(uint32_t*)p0          = pack2h(h0, h1);
        *(uint32_t*)(p0 + 1024) = pack2h(lo0, lo1);
        split2h(v2, h0, lo0); split2h(v3, h1, lo1);
        __half* p1 = g_atts + (mrow + 8) * K2 + hh * 64 + d;
        *(uint32_t*)p1          = pack2h(h0, h1);
        *(uint32_t*)(p1 + 1024) = pack2h(lo0, lo1);
    }
}

// ---------------------------------------------------------------------------
extern "C" void kernel_launch(void* const* d_in, const int* in_sizes, int n_in,
                              void* d_out, int out_size)
{
    const float* x  = (const float*)d_in[0];
    // d_in[1] = att_mask (causal tril) — applied analytically
    const float* wq = (const float*)d_in[2];
    const float* bq = (const float*)d_in[3];
    const float* wk = (const float*)d_in[4];
    const float* bk = (const float*)d_in[5];
    const float* wv = (const float*)d_in[6];
    const float* bv = (const float*)d_in[7];
    const float* wp = (const float*)d_in[8];
    const float* bp = (const float*)d_in[9];
    float* out = (float*)d_out;

    __half *xs, *wcat, *atts;
    cudaGetSymbolAddress((void**)&xs,   g_xs);
    cudaGetSymbolAddress((void**)&wcat, g_wcat);
    cudaGetSymbolAddress((void**)&atts, g_atts);

    cudaFuncSetAttribute(hmma_gemm<0>, cudaFuncAttributeMaxDynamicSharedMemorySize, GEMM_SMEM);
    cudaFuncSetAttribute(hmma_gemm<1>, cudaFuncAttributeMaxDynamicSharedMemorySize, GEMM_SMEM);
    cudaFuncSetAttribute(attn_kernel,  cudaFuncAttributeMaxDynamicSharedMemorySize, ATT_SMEM);

    // 1) fp16 hi/lo splits
    split_x_kernel<<<MTOT, 256>>>(x, xs);
    {
        W4 w;
        w.in[0] = wq; w.in[1] = wk; w.in[2] = wv; w.in[3] = wp;
        dim3 grid(CC, 4);
        split_w4_kernel<<<grid, 256>>>(w);
    }

    // 2) QKV projections (fp16 2-term HMMA) -> bf16 Q'/K'/V' [h|l] layouts
    {
        GemmP p;
        p.A = xs;
        p.W[0] = wcat + 0 * (size_t)WSZ2; p.bias[0] = bq;
        p.W[1] = wcat + 1 * (size_t)WSZ2; p.bias[1] = bk;
        p.W[2] = wcat + 2 * (size_t)WSZ2; p.bias[2] = bv;
        p.fout = nullptr;
        dim3 grid(CC / 128, MTOT / 128, 3);
        hmma_gemm<1><<<grid, 256, GEMM_SMEM>>>(p);
    }

    // 3) Causal flash attention (bf16 HMMA, split-KV warp groups) -> g_atts fp16 [h|l]
    {
        dim3 grid(TT / 64, BB * HH);
        attn_kernel<<<grid, 256, ATT_SMEM>>>();
    }

    // 4) Output projection (fp16 2-term HMMA) -> d_out
    {
        GemmP p;
        p.A = atts;
        p.W[0] = wcat + 3 * (size_t)WSZ2; p.bias[0] = bp;
        p.W[1] = p.W[0]; p.bias[1] = bp;
        p.W[2] = p.W[0]; p.bias[2] = bp;
        p.fout = out;
        dim3 grid(CC / 128, MTOT / 128, 1);
        hmma_gemm<0><<<grid, 256, GEMM_SMEM>>>(p);
    }
}